// round 1
// baseline (speedup 1.0000x reference)
#include <cuda_runtime.h>
#include <math.h>

#define Tq 1536
#define CC 1536
#define T2 3071
#define NH 8
#define KH 64
#define VH 192
#define FF 192
#define HK 512
#define HV 1536
#define D1 3072

// ---------------- scratch (device globals; no allocation allowed) ----------------
__device__ __align__(128) float g_xn[Tq * CC];
__device__ __align__(128) float g_q[Tq * HK];
__device__ __align__(128) float g_k[Tq * HK];
__device__ __align__(128) float g_v[Tq * HV];
__device__ __align__(128) float g_pos[T2 * FF];
__device__ __align__(128) float g_rk[T2 * HK];
__device__ __align__(128) float g_logits[(size_t)NH * Tq * Tq];   // 18.9M floats
__device__ __align__(128) float g_rel[(size_t)NH * Tq * T2];      // 37.7M floats
__device__ __align__(128) float g_o[Tq * HV];
__device__ __align__(128) float g_y[Tq * CC];
__device__ __align__(128) float g_yn[Tq * CC];
__device__ __align__(128) float g_h1[Tq * D1];

// ---------------- layernorm (one block per row, 256 threads) ----------------
__global__ void ln_kernel(const float* __restrict__ x, const float* __restrict__ g,
                          const float* __restrict__ b, float* __restrict__ out) {
    int row = blockIdx.x;
    int tid = threadIdx.x;
    const float* xr = x + (size_t)row * CC;
    float v[6];
    float s = 0.f, s2 = 0.f;
#pragma unroll
    for (int e = 0; e < 6; e++) {
        float t = xr[tid + 256 * e];
        v[e] = t; s += t; s2 += t * t;
    }
    __shared__ float sh[16];
#pragma unroll
    for (int o = 16; o > 0; o >>= 1) {
        s  += __shfl_xor_sync(0xffffffffu, s, o);
        s2 += __shfl_xor_sync(0xffffffffu, s2, o);
    }
    int wid = tid >> 5, lane = tid & 31;
    if (lane == 0) { sh[wid] = s; sh[8 + wid] = s2; }
    __syncthreads();
    if (tid == 0) {
        float a = 0.f, c = 0.f;
        for (int i = 0; i < 8; i++) { a += sh[i]; c += sh[8 + i]; }
        sh[0] = a; sh[8] = c;
    }
    __syncthreads();
    float mu  = sh[0] * (1.f / CC);
    float var = sh[8] * (1.f / CC) - mu * mu;
    float rs  = rsqrtf(var + 1e-3f);
#pragma unroll
    for (int e = 0; e < 6; e++) {
        int c = tid + 256 * e;
        out[(size_t)row * CC + c] = (v[e] - mu) * rs * g[c] + b[c];
    }
}

// ---------------- generic tiled fp32 SGEMM (NN), batched, fused epilogue ----------------
// C = relu_opt( (A@B)*scale + bias ) + resid
__global__ void sgemm_nn(const float* __restrict__ A, int lda, long long sA,
                         const float* __restrict__ B, int ldb, long long sB,
                         float* __restrict__ C, int ldc, long long sC,
                         int M, int N, int Kd,
                         const float* __restrict__ bias,
                         const float* __restrict__ resid,
                         float scale, int do_relu) {
    A += (long long)blockIdx.z * sA;
    B += (long long)blockIdx.z * sB;
    C += (long long)blockIdx.z * sC;
    const float* R = resid ? resid + (long long)blockIdx.z * sC : nullptr;
    __shared__ float As[16][64];
    __shared__ float Bs[16][64];
    int tid = threadIdx.x;             // 256
    int tx = tid & 15, ty = tid >> 4;
    int row0 = blockIdx.y * 64, col0 = blockIdx.x * 64;
    int am = tid >> 2;                 // 0..63
    int ak = (tid & 3) * 4;            // 0,4,8,12
    int arow = row0 + am; if (arow >= M) arow = M - 1;
    int bk = tid >> 4;                 // 0..15
    int bn = (tid & 15) * 4;           // 0..60
    float acc[4][4] = {};
    for (int k0 = 0; k0 < Kd; k0 += 16) {
        float4 av = *(const float4*)(A + (size_t)arow * lda + k0 + ak);
        float4 bv = *(const float4*)(B + (size_t)(k0 + bk) * ldb + col0 + bn);
        As[ak + 0][am] = av.x; As[ak + 1][am] = av.y;
        As[ak + 2][am] = av.z; As[ak + 3][am] = av.w;
        *(float4*)(&Bs[bk][bn]) = bv;
        __syncthreads();
#pragma unroll
        for (int kk = 0; kk < 16; kk++) {
            float4 a4 = *(const float4*)(&As[kk][ty * 4]);
            float4 b4 = *(const float4*)(&Bs[kk][tx * 4]);
            float a[4] = {a4.x, a4.y, a4.z, a4.w};
            float bb[4] = {b4.x, b4.y, b4.z, b4.w};
#pragma unroll
            for (int i = 0; i < 4; i++)
#pragma unroll
                for (int j = 0; j < 4; j++)
                    acc[i][j] += a[i] * bb[j];
        }
        __syncthreads();
    }
#pragma unroll
    for (int i = 0; i < 4; i++) {
        int r = row0 + ty * 4 + i;
        if (r >= M) break;
#pragma unroll
        for (int j = 0; j < 4; j++) {
            int cn = col0 + tx * 4 + j;
            float t = acc[i][j] * scale;
            if (bias) t += bias[cn];
            if (do_relu) t = fmaxf(t, 0.f);
            if (R) t += R[(size_t)r * ldc + cn];
            C[(size_t)r * ldc + cn] = t;
        }
    }
}

// ---------------- per-head NT gemm: C[h,q,n] = sum_c (Q[q,h,c]+bias[h,c]) * Bm[n,h,c] ----------------
__global__ void qk_kernel(const float* __restrict__ Q, const float* __restrict__ bias,
                          const float* __restrict__ Bm, float* __restrict__ Cc,
                          int N, int ldc, long long strideC) {
    int h = blockIdx.z;
    int q0 = blockIdx.y * 32, n0 = blockIdx.x * 32;
    __shared__ float Qs[32][65];
    __shared__ float Bs[32][65];
    __shared__ float bs[64];
    int tid = threadIdx.x;             // 256
    if (tid < 64) bs[tid] = bias[h * 64 + tid];
    __syncthreads();
#pragma unroll
    for (int e = 0; e < 8; e++) {
        int idx = tid + 256 * e;       // 0..2047
        int r = idx >> 6, c = idx & 63;
        Qs[r][c] = Q[(size_t)(q0 + r) * HK + h * 64 + c] + bs[c];
        int n = n0 + r;
        Bs[r][c] = (n < N) ? Bm[(size_t)n * HK + h * 64 + c] : 0.f;
    }
    __syncthreads();
    int tx = tid & 15, ty = tid >> 4;
    float acc[2][2] = {};
#pragma unroll
    for (int c = 0; c < 64; c++) {
        float a0 = Qs[ty * 2][c],     a1 = Qs[ty * 2 + 1][c];
        float b0 = Bs[tx * 2][c],     b1 = Bs[tx * 2 + 1][c];
        acc[0][0] += a0 * b0; acc[0][1] += a0 * b1;
        acc[1][0] += a1 * b0; acc[1][1] += a1 * b1;
    }
    long long base = (long long)h * strideC;
#pragma unroll
    for (int i = 0; i < 2; i++)
#pragma unroll
        for (int j = 0; j < 2; j++) {
            int qq = q0 + ty * 2 + i, n = n0 + tx * 2 + j;
            if (n < N) Cc[base + (size_t)qq * ldc + n] = acc[i][j];
        }
}

// ---------------- positional features: one warp per position ----------------
__global__ void posfeat_kernel(float* __restrict__ pos) {
    int warp = threadIdx.x >> 5, lane = threadIdx.x & 31;
    int p = blockIdx.x * 8 + warp;
    if (p >= T2) return;
    float d = (float)(p - (Tq - 1));
    float ap = fabsf(d);
    float sgn = (d > 0.f) ? 1.f : ((d < 0.f) ? -1.f : 0.f);
    // exponential half-life features
    double hi = 10.584962500721156;    // log2(1536)
    double exx = 3.0 + (hi - 3.0) * (double)lane / 31.0;
    float half_life = (float)exp2(exx);
    float coef = (float)(-(0.6931471805599453 / (double)half_life));
    float fexp = expf(ap * coef);
    // central mask
    float width = exp2f((float)(lane + 1)) - 1.f;
    float fcm = (width > ap) ? 1.f : 0.f;
    // gamma pdf bumps
    double mean = 48.0 + (1536.0 - 48.0) * (double)lane / 31.0;
    float conc = (float)((mean / 24.0) * (mean / 24.0));
    float rate = (float)(mean / 576.0);
    float log_unnorm = (conc - 1.f) * logf(ap) - rate * ap;   // -inf at ap=0 -> exp = 0 (matches xlogy path)
    float log_norm = lgammaf(conc) - conc * logf(rate);
    float prob = expf(log_unnorm - log_norm) + 1e-8f;
    float mx = prob;
#pragma unroll
    for (int o = 16; o > 0; o >>= 1) mx = fmaxf(mx, __shfl_xor_sync(0xffffffffu, mx, o));
    float fg = prob / mx;
    float* row = pos + (size_t)p * FF;
    row[lane]       = fexp;
    row[32 + lane]  = fcm;
    row[64 + lane]  = fg;
    row[96 + lane]  = sgn * fexp;
    row[128 + lane] = sgn * fcm;
    row[160 + lane] = sgn * fg;
}

// ---------------- logits += shifted(rel); softmax in place ----------------
// shifted[q,j] = rel[h,q, (T-1) + j - q]
__global__ void shift_softmax_kernel(float* __restrict__ logits, const float* __restrict__ rel) {
    int q = blockIdx.x, h = blockIdx.y;
    int tid = threadIdx.x;             // 256
    float* row = logits + ((size_t)h * Tq + q) * Tq;
    const float* rrow = rel + ((size_t)h * Tq + q) * T2 + (Tq - 1 - q);
    float v[6];
    float mx = -1e30f;
#pragma unroll
    for (int e = 0; e < 6; e++) {
        int j = tid + 256 * e;
        v[e] = row[j] + rrow[j];
        mx = fmaxf(mx, v[e]);
    }
    __shared__ float sh[8];
#pragma unroll
    for (int o = 16; o > 0; o >>= 1) mx = fmaxf(mx, __shfl_xor_sync(0xffffffffu, mx, o));
    int wid = tid >> 5, lane = tid & 31;
    if (lane == 0) sh[wid] = mx;
    __syncthreads();
    if (tid == 0) { float m = sh[0]; for (int i = 1; i < 8; i++) m = fmaxf(m, sh[i]); sh[0] = m; }
    __syncthreads();
    mx = sh[0];
    __syncthreads();
    float s = 0.f;
#pragma unroll
    for (int e = 0; e < 6; e++) { v[e] = expf(v[e] - mx); s += v[e]; }
#pragma unroll
    for (int o = 16; o > 0; o >>= 1) s += __shfl_xor_sync(0xffffffffu, s, o);
    if (lane == 0) sh[wid] = s;
    __syncthreads();
    if (tid == 0) { float m = 0.f; for (int i = 0; i < 8; i++) m += sh[i]; sh[0] = m; }
    __syncthreads();
    float inv = 1.f / sh[0];
#pragma unroll
    for (int e = 0; e < 6; e++) row[tid + 256 * e] = v[e] * inv;
}

// ---------------- host orchestration ----------------
extern "C" void kernel_launch(void* const* d_in, const int* in_sizes, int n_in,
                              void* d_out, int out_size) {
    (void)in_sizes; (void)n_in; (void)out_size;
    const float* x     = (const float*)d_in[0];
    const float* ln1_g = (const float*)d_in[1];
    const float* ln1_b = (const float*)d_in[2];
    const float* ln2_g = (const float*)d_in[3];
    const float* ln2_b = (const float*)d_in[4];
    const float* Wq    = (const float*)d_in[5];
    const float* Wk    = (const float*)d_in[6];
    const float* Wv    = (const float*)d_in[7];
    const float* Wr    = (const float*)d_in[8];
    const float* Wo    = (const float*)d_in[9];
    const float* bo    = (const float*)d_in[10];
    const float* rwb   = (const float*)d_in[11];
    const float* rrb   = (const float*)d_in[12];
    const float* W1    = (const float*)d_in[13];
    const float* b1    = (const float*)d_in[14];
    const float* W2    = (const float*)d_in[15];
    const float* b2    = (const float*)d_in[16];
    float* out = (float*)d_out;

    float *xn, *q, *k, *v, *pos, *rk, *logits, *rel, *o, *y, *yn, *h1;
    cudaGetSymbolAddress((void**)&xn, g_xn);
    cudaGetSymbolAddress((void**)&q, g_q);
    cudaGetSymbolAddress((void**)&k, g_k);
    cudaGetSymbolAddress((void**)&v, g_v);
    cudaGetSymbolAddress((void**)&pos, g_pos);
    cudaGetSymbolAddress((void**)&rk, g_rk);
    cudaGetSymbolAddress((void**)&logits, g_logits);
    cudaGetSymbolAddress((void**)&rel, g_rel);
    cudaGetSymbolAddress((void**)&o, g_o);
    cudaGetSymbolAddress((void**)&y, g_y);
    cudaGetSymbolAddress((void**)&yn, g_yn);
    cudaGetSymbolAddress((void**)&h1, g_h1);

    // 1) LN1
    ln_kernel<<<Tq, 256>>>(x, ln1_g, ln1_b, xn);
    // 2) projections  (q scaled by K^-0.5 = 0.125)
    sgemm_nn<<<dim3(HK / 64, Tq / 64, 1), 256>>>(xn, CC, 0, Wq, HK, 0, q, HK, 0,
                                                 Tq, HK, CC, nullptr, nullptr, 0.125f, 0);
    sgemm_nn<<<dim3(HK / 64, Tq / 64, 1), 256>>>(xn, CC, 0, Wk, HK, 0, k, HK, 0,
                                                 Tq, HK, CC, nullptr, nullptr, 1.f, 0);
    sgemm_nn<<<dim3(HV / 64, Tq / 64, 1), 256>>>(xn, CC, 0, Wv, HV, 0, v, HV, 0,
                                                 Tq, HV, CC, nullptr, nullptr, 1.f, 0);
    // 3) positional features + r_k projection
    posfeat_kernel<<<(T2 + 7) / 8, 256>>>(pos);
    sgemm_nn<<<dim3(HK / 64, (T2 + 63) / 64, 1), 256>>>(pos, FF, 0, Wr, HK, 0, rk, HK, 0,
                                                        T2, HK, FF, nullptr, nullptr, 1.f, 0);
    // 4) content logits + relative logits
    qk_kernel<<<dim3(Tq / 32, Tq / 32, NH), 256>>>(q, rwb, k, logits, Tq, Tq, (long long)Tq * Tq);
    qk_kernel<<<dim3((T2 + 31) / 32, Tq / 32, NH), 256>>>(q, rrb, rk, rel, T2, T2, (long long)Tq * T2);
    // 5) shift + softmax (in place over logits)
    shift_softmax_kernel<<<dim3(Tq, NH), 256>>>(logits, rel);
    // 6) attn @ V (batched over heads)
    sgemm_nn<<<dim3(VH / 64, Tq / 64, NH), 256>>>(logits, Tq, (long long)Tq * Tq,
                                                  v, HV, VH,
                                                  o, HV, VH,
                                                  Tq, VH, Tq, nullptr, nullptr, 1.f, 0);
    // 7) output projection + residual: y = x + o@Wo + bo
    sgemm_nn<<<dim3(CC / 64, Tq / 64, 1), 256>>>(o, HV, 0, Wo, CC, 0, y, CC, 0,
                                                 Tq, CC, HV, bo, x, 1.f, 0);
    // 8) LN2 + MLP
    ln_kernel<<<Tq, 256>>>(y, ln2_g, ln2_b, yn);
    sgemm_nn<<<dim3(D1 / 64, Tq / 64, 1), 256>>>(yn, CC, 0, W1, D1, 0, h1, D1, 0,
                                                 Tq, D1, CC, b1, nullptr, 1.f, 1);
    sgemm_nn<<<dim3(CC / 64, Tq / 64, 1), 256>>>(h1, D1, 0, W2, CC, 0, out, CC, 0,
                                                 Tq, CC, D1, b2, y, 1.f, 0);
}

// round 2
// speedup vs baseline: 1.3564x; 1.3564x over previous
#include <cuda_runtime.h>
#include <math.h>

#define Tq 1536
#define CC 1536
#define T2 3071
#define NH 8
#define KH 64
#define VH 192
#define FF 192
#define HK 512
#define HV 1536
#define D1 3072

// ---------------- scratch ----------------
__device__ __align__(128) float g_xn[Tq * CC];
__device__ __align__(128) float g_q[Tq * HK];
__device__ __align__(128) float g_k[Tq * HK];
__device__ __align__(128) float g_v[Tq * HV];
__device__ __align__(128) float g_pos[(T2 + 1) * FF];
__device__ __align__(128) float g_rk[(T2 + 1) * HK];
__device__ __align__(128) float g_logits[(size_t)NH * Tq * Tq];
__device__ __align__(128) float g_o[Tq * HV];
__device__ __align__(128) float g_y[Tq * CC];
__device__ __align__(128) float g_yn[Tq * CC];
__device__ __align__(128) float g_h1[Tq * D1];

// ---------------- layernorm ----------------
__global__ void ln_kernel(const float* __restrict__ x, const float* __restrict__ g,
                          const float* __restrict__ b, float* __restrict__ out) {
    int row = blockIdx.x;
    int tid = threadIdx.x;
    const float* xr = x + (size_t)row * CC;
    float v[6];
    float s = 0.f, s2 = 0.f;
#pragma unroll
    for (int e = 0; e < 6; e++) {
        float t = xr[tid + 256 * e];
        v[e] = t; s += t; s2 += t * t;
    }
    __shared__ float sh[16];
#pragma unroll
    for (int o = 16; o > 0; o >>= 1) {
        s  += __shfl_xor_sync(0xffffffffu, s, o);
        s2 += __shfl_xor_sync(0xffffffffu, s2, o);
    }
    int wid = tid >> 5, lane = tid & 31;
    if (lane == 0) { sh[wid] = s; sh[8 + wid] = s2; }
    __syncthreads();
    if (tid == 0) {
        float a = 0.f, c = 0.f;
        for (int i = 0; i < 8; i++) { a += sh[i]; c += sh[8 + i]; }
        sh[0] = a; sh[8] = c;
    }
    __syncthreads();
    float mu  = sh[0] * (1.f / CC);
    float var = sh[8] * (1.f / CC) - mu * mu;
    float rs  = rsqrtf(var + 1e-3f);
#pragma unroll
    for (int e = 0; e < 6; e++) {
        int c = tid + 256 * e;
        out[(size_t)row * CC + c] = (v[e] - mu) * rs * g[c] + b[c];
    }
}

// ---------------- GEMM core: 128xBN x16 tile, 8x(BN/16) micro, double-buffered ----------------
template<int BN>
__device__ __forceinline__ void gemm_core(
    float* sA, float* sB,
    const float* __restrict__ A, int lda,
    const float* __restrict__ B, int ldb,
    float* __restrict__ C, int ldc,
    int M, int Kd, int row0, int col0,
    const float* __restrict__ bias,
    const float* __restrict__ resid,
    float scale, int do_relu)
{
    constexpr int TN = BN / 16;     // 8 or 4
    constexpr int BE = BN / 64;     // float4 loads per thread for B: 2 or 1
    const int tid = threadIdx.x;
    const int tx = tid & 15, ty = tid >> 4;
    const int a_row = tid >> 2;         // 0..63 (+64)
    const int a_k = (tid & 3) * 4;      // 0,4,8,12

    float acc[8][TN];
#pragma unroll
    for (int i = 0; i < 8; i++)
#pragma unroll
        for (int j = 0; j < TN; j++) acc[i][j] = 0.f;

    float4 ar[2], br[BE];
    // prologue: stage 0
#pragma unroll
    for (int e = 0; e < 2; e++) {
        int r = row0 + a_row + e * 64;
        if (r >= M) r = M - 1;
        ar[e] = *(const float4*)(A + (size_t)r * lda + a_k);
    }
#pragma unroll
    for (int e = 0; e < BE; e++) {
        int id = tid + e * 256;
        int krow = id / (BN / 4);
        int cn = (id % (BN / 4)) * 4;
        br[e] = *(const float4*)(B + (size_t)krow * ldb + col0 + cn);
    }
#pragma unroll
    for (int e = 0; e < 2; e++) {
        int r = a_row + e * 64;
        sA[(a_k + 0) * 132 + r] = ar[e].x;
        sA[(a_k + 1) * 132 + r] = ar[e].y;
        sA[(a_k + 2) * 132 + r] = ar[e].z;
        sA[(a_k + 3) * 132 + r] = ar[e].w;
    }
#pragma unroll
    for (int e = 0; e < BE; e++) {
        int id = tid + e * 256;
        int krow = id / (BN / 4);
        int cn = (id % (BN / 4)) * 4;
        *(float4*)(&sB[krow * BN + cn]) = br[e];
    }
    __syncthreads();
    int buf = 0;
    for (int k0 = 0; k0 < Kd; k0 += 16) {
        bool has_next = (k0 + 16 < Kd);
        if (has_next) {
#pragma unroll
            for (int e = 0; e < 2; e++) {
                int r = row0 + a_row + e * 64;
                if (r >= M) r = M - 1;
                ar[e] = *(const float4*)(A + (size_t)r * lda + k0 + 16 + a_k);
            }
#pragma unroll
            for (int e = 0; e < BE; e++) {
                int id = tid + e * 256;
                int krow = id / (BN / 4);
                int cn = (id % (BN / 4)) * 4;
                br[e] = *(const float4*)(B + (size_t)(k0 + 16 + krow) * ldb + col0 + cn);
            }
        }
        const float* As = sA + buf * 16 * 132;
        const float* Bs = sB + buf * 16 * BN;
#pragma unroll
        for (int kk = 0; kk < 16; kk++) {
            float4 a0 = *(const float4*)(As + kk * 132 + ty * 4);
            float4 a1 = *(const float4*)(As + kk * 132 + ty * 4 + 64);
            float av[8] = {a0.x, a0.y, a0.z, a0.w, a1.x, a1.y, a1.z, a1.w};
            float bv[TN];
            float4 b0 = *(const float4*)(Bs + kk * BN + tx * 4);
            bv[0] = b0.x; bv[1] = b0.y; bv[2] = b0.z; bv[3] = b0.w;
            if constexpr (TN == 8) {
                float4 b1 = *(const float4*)(Bs + kk * BN + tx * 4 + 64);
                bv[4] = b1.x; bv[5] = b1.y; bv[6] = b1.z; bv[7] = b1.w;
            }
#pragma unroll
            for (int i = 0; i < 8; i++)
#pragma unroll
                for (int j = 0; j < TN; j++)
                    acc[i][j] += av[i] * bv[j];
        }
        if (has_next) {
            int nb = buf ^ 1;
#pragma unroll
            for (int e = 0; e < 2; e++) {
                int r = a_row + e * 64;
                sA[(nb * 16 + a_k + 0) * 132 + r] = ar[e].x;
                sA[(nb * 16 + a_k + 1) * 132 + r] = ar[e].y;
                sA[(nb * 16 + a_k + 2) * 132 + r] = ar[e].z;
                sA[(nb * 16 + a_k + 3) * 132 + r] = ar[e].w;
            }
#pragma unroll
            for (int e = 0; e < BE; e++) {
                int id = tid + e * 256;
                int krow = id / (BN / 4);
                int cn = (id % (BN / 4)) * 4;
                *(float4*)(&sB[(nb * 16 + krow) * BN + cn]) = br[e];
            }
            __syncthreads();
            buf = nb;
        }
    }
    // epilogue
#pragma unroll
    for (int i = 0; i < 8; i++) {
        int r = row0 + ty * 4 + (i & 3) + (i >> 2) * 64;
        if (r >= M) continue;
#pragma unroll
        for (int jb = 0; jb < TN / 4; jb++) {
            int cn = col0 + tx * 4 + jb * 64;
            float4 t = make_float4(acc[i][jb * 4 + 0], acc[i][jb * 4 + 1],
                                   acc[i][jb * 4 + 2], acc[i][jb * 4 + 3]);
            t.x *= scale; t.y *= scale; t.z *= scale; t.w *= scale;
            if (bias) {
                float4 bb = *(const float4*)(bias + cn);
                t.x += bb.x; t.y += bb.y; t.z += bb.z; t.w += bb.w;
            }
            if (do_relu) {
                t.x = fmaxf(t.x, 0.f); t.y = fmaxf(t.y, 0.f);
                t.z = fmaxf(t.z, 0.f); t.w = fmaxf(t.w, 0.f);
            }
            if (resid) {
                float4 rr = *(const float4*)(resid + (size_t)r * ldc + cn);
                t.x += rr.x; t.y += rr.y; t.z += rr.z; t.w += rr.w;
            }
            *(float4*)(C + (size_t)r * ldc + cn) = t;
        }
    }
}

template<int BN>
__global__ void __launch_bounds__(256, 2) sgemm_nn(
    const float* __restrict__ A, int lda, long long strA,
    const float* __restrict__ B, int ldb, long long strB,
    float* __restrict__ C, int ldc, long long strC,
    int M, int Kd,
    const float* __restrict__ bias,
    const float* __restrict__ resid,
    float scale, int do_relu)
{
    __shared__ float sA[2 * 16 * 132];
    __shared__ float sB[2 * 16 * BN];
    const float* Ab = A + (long long)blockIdx.z * strA;
    const float* Bb = B + (long long)blockIdx.z * strB;
    float* Cb = C + (long long)blockIdx.z * strC;
    const float* Rb = resid ? resid + (long long)blockIdx.z * strC : nullptr;
    gemm_core<BN>(sA, sB, Ab, lda, Bb, ldb, Cb, ldc, M, Kd,
                  blockIdx.y * 128, blockIdx.x * BN, bias, Rb, scale, do_relu);
}

// fused QKV: grid.x 0..19 -> [Wq:4][Wk:4][Wv:12] column blocks
__global__ void __launch_bounds__(256, 2) qkv_kernel(
    const float* __restrict__ xn,
    const float* __restrict__ Wq, const float* __restrict__ Wk, const float* __restrict__ Wv,
    float* __restrict__ q, float* __restrict__ k, float* __restrict__ v)
{
    __shared__ float sA[2 * 16 * 132];
    __shared__ float sB[2 * 16 * 128];
    int bx = blockIdx.x;
    int row0 = blockIdx.y * 128;
    if (bx < 4)
        gemm_core<128>(sA, sB, xn, CC, Wq, HK, q, HK, Tq, CC, row0, bx * 128,
                       nullptr, nullptr, 0.125f, 0);
    else if (bx < 8)
        gemm_core<128>(sA, sB, xn, CC, Wk, HK, k, HK, Tq, CC, row0, (bx - 4) * 128,
                       nullptr, nullptr, 1.f, 0);
    else
        gemm_core<128>(sA, sB, xn, CC, Wv, HV, v, HV, Tq, CC, row0, (bx - 8) * 128,
                       nullptr, nullptr, 1.f, 0);
}

// ---------------- NT qk gemm: 128x128, K=64, bias on A; SHIFT=1 accumulates shifted into C ----------------
template<int SHIFT>
__global__ void __launch_bounds__(256, 2) qk128(
    const float* __restrict__ Q, const float* __restrict__ bias,
    const float* __restrict__ Bm, float* __restrict__ Cc, int N)
{
    __shared__ float As[32 * 132];
    __shared__ float Bs[32 * 132];
    int h = blockIdx.z;
    int tid = threadIdx.x;
    int tx = tid & 15, ty = tid >> 4;
    int q0 = blockIdx.y * 128, n0 = blockIdx.x * 128;
    int l_c4 = (tid & 7) * 4;      // 0..28 within 32-chunk

    float acc[8][8];
#pragma unroll
    for (int i = 0; i < 8; i++)
#pragma unroll
        for (int j = 0; j < 8; j++) acc[i][j] = 0.f;

#pragma unroll
    for (int kh = 0; kh < 2; kh++) {
        int cbase = h * 64 + kh * 32 + l_c4;
        float4 bq = *(const float4*)(bias + cbase);
        __syncthreads();
#pragma unroll
        for (int e = 0; e < 4; e++) {
            int row = (tid >> 3) + 32 * e;
            float4 a = *(const float4*)(Q + (size_t)(q0 + row) * HK + cbase);
            As[(l_c4 + 0) * 132 + row] = a.x + bq.x;
            As[(l_c4 + 1) * 132 + row] = a.y + bq.y;
            As[(l_c4 + 2) * 132 + row] = a.z + bq.z;
            As[(l_c4 + 3) * 132 + row] = a.w + bq.w;
            int n = n0 + row;
            int nc = n < N ? n : N - 1;
            float4 b = *(const float4*)(Bm + (size_t)nc * HK + cbase);
            Bs[(l_c4 + 0) * 132 + row] = b.x;
            Bs[(l_c4 + 1) * 132 + row] = b.y;
            Bs[(l_c4 + 2) * 132 + row] = b.z;
            Bs[(l_c4 + 3) * 132 + row] = b.w;
        }
        __syncthreads();
#pragma unroll
        for (int kk = 0; kk < 32; kk++) {
            float4 a0 = *(const float4*)(As + kk * 132 + ty * 4);
            float4 a1 = *(const float4*)(As + kk * 132 + ty * 4 + 64);
            float4 b0 = *(const float4*)(Bs + kk * 132 + tx * 4);
            float4 b1 = *(const float4*)(Bs + kk * 132 + tx * 4 + 64);
            float av[8] = {a0.x, a0.y, a0.z, a0.w, a1.x, a1.y, a1.z, a1.w};
            float bv[8] = {b0.x, b0.y, b0.z, b0.w, b1.x, b1.y, b1.z, b1.w};
#pragma unroll
            for (int i = 0; i < 8; i++)
#pragma unroll
                for (int j = 0; j < 8; j++)
                    acc[i][j] += av[i] * bv[j];
        }
    }
#pragma unroll
    for (int i = 0; i < 8; i++) {
        int qq = q0 + ty * 4 + (i & 3) + (i >> 2) * 64;
        float* row = Cc + ((size_t)h * Tq + qq) * (size_t)(SHIFT ? Tq : Tq);
        if constexpr (SHIFT) {
            // logits[h,q,j] += rel[h,q,n], j = n - (T-1) + q
            int shift = qq - (Tq - 1);
#pragma unroll
            for (int jb = 0; jb < 2; jb++) {
                int n = n0 + tx * 4 + jb * 64;
                int j = n + shift;
#pragma unroll
                for (int qx = 0; qx < 4; qx++) {
                    int jj = j + qx;
                    if (jj >= 0 && jj < Tq) row[jj] += acc[i][jb * 4 + qx];
                }
            }
        } else {
#pragma unroll
            for (int jb = 0; jb < 2; jb++) {
                int n = n0 + tx * 4 + jb * 64;
                float4 t = make_float4(acc[i][jb * 4 + 0], acc[i][jb * 4 + 1],
                                       acc[i][jb * 4 + 2], acc[i][jb * 4 + 3]);
                *(float4*)(row + n) = t;
            }
        }
    }
}

// ---------------- positional features ----------------
__global__ void posfeat_kernel(float* __restrict__ pos) {
    int warp = threadIdx.x >> 5, lane = threadIdx.x & 31;
    int p = blockIdx.x * 8 + warp;
    if (p >= T2) return;
    float d = (float)(p - (Tq - 1));
    float ap = fabsf(d);
    float sgn = (d > 0.f) ? 1.f : ((d < 0.f) ? -1.f : 0.f);
    double hi = 10.584962500721156;    // log2(1536)
    double exx = 3.0 + (hi - 3.0) * (double)lane / 31.0;
    float half_life = (float)exp2(exx);
    float coef = (float)(-(0.6931471805599453 / (double)half_life));
    float fexp = expf(ap * coef);
    float width = exp2f((float)(lane + 1)) - 1.f;
    float fcm = (width > ap) ? 1.f : 0.f;
    double mean = 48.0 + (1536.0 - 48.0) * (double)lane / 31.0;
    float conc = (float)((mean / 24.0) * (mean / 24.0));
    float rate = (float)(mean / 576.0);
    float log_unnorm = (conc - 1.f) * logf(ap) - rate * ap;
    float log_norm = lgammaf(conc) - conc * logf(rate);
    float prob = expf(log_unnorm - log_norm) + 1e-8f;
    float mx = prob;
#pragma unroll
    for (int o = 16; o > 0; o >>= 1) mx = fmaxf(mx, __shfl_xor_sync(0xffffffffu, mx, o));
    float fg = prob / mx;
    float* row = pos + (size_t)p * FF;
    row[lane]       = fexp;
    row[32 + lane]  = fcm;
    row[64 + lane]  = fg;
    row[96 + lane]  = sgn * fexp;
    row[128 + lane] = sgn * fcm;
    row[160 + lane] = sgn * fg;
}

// ---------------- softmax in place over logits rows ----------------
__global__ void softmax_kernel(float* __restrict__ logits) {
    int q = blockIdx.x, h = blockIdx.y;
    int tid = threadIdx.x;
    float* row = logits + ((size_t)h * Tq + q) * Tq;
    float v[6];
    float mx = -1e30f;
#pragma unroll
    for (int e = 0; e < 6; e++) {
        v[e] = row[tid + 256 * e];
        mx = fmaxf(mx, v[e]);
    }
    __shared__ float sh[8];
#pragma unroll
    for (int o = 16; o > 0; o >>= 1) mx = fmaxf(mx, __shfl_xor_sync(0xffffffffu, mx, o));
    int wid = tid >> 5, lane = tid & 31;
    if (lane == 0) sh[wid] = mx;
    __syncthreads();
    if (tid == 0) { float m = sh[0]; for (int i = 1; i < 8; i++) m = fmaxf(m, sh[i]); sh[0] = m; }
    __syncthreads();
    mx = sh[0];
    __syncthreads();
    float s = 0.f;
#pragma unroll
    for (int e = 0; e < 6; e++) { v[e] = expf(v[e] - mx); s += v[e]; }
#pragma unroll
    for (int o = 16; o > 0; o >>= 1) s += __shfl_xor_sync(0xffffffffu, s, o);
    if (lane == 0) sh[wid] = s;
    __syncthreads();
    if (tid == 0) { float m = 0.f; for (int i = 0; i < 8; i++) m += sh[i]; sh[0] = m; }
    __syncthreads();
    float inv = 1.f / sh[0];
#pragma unroll
    for (int e = 0; e < 6; e++) row[tid + 256 * e] = v[e] * inv;
}

// ---------------- host ----------------
extern "C" void kernel_launch(void* const* d_in, const int* in_sizes, int n_in,
                              void* d_out, int out_size) {
    (void)in_sizes; (void)n_in; (void)out_size;
    const float* x     = (const float*)d_in[0];
    const float* ln1_g = (const float*)d_in[1];
    const float* ln1_b = (const float*)d_in[2];
    const float* ln2_g = (const float*)d_in[3];
    const float* ln2_b = (const float*)d_in[4];
    const float* Wq    = (const float*)d_in[5];
    const float* Wk    = (const float*)d_in[6];
    const float* Wv    = (const float*)d_in[7];
    const float* Wr    = (const float*)d_in[8];
    const float* Wo    = (const float*)d_in[9];
    const float* bo    = (const float*)d_in[10];
    const float* rwb   = (const float*)d_in[11];
    const float* rrb   = (const float*)d_in[12];
    const float* W1    = (const float*)d_in[13];
    const float* b1    = (const float*)d_in[14];
    const float* W2    = (const float*)d_in[15];
    const float* b2    = (const float*)d_in[16];
    float* out = (float*)d_out;

    float *xn, *q, *k, *v, *pos, *rk, *logits, *o, *y, *yn, *h1;
    cudaGetSymbolAddress((void**)&xn, g_xn);
    cudaGetSymbolAddress((void**)&q, g_q);
    cudaGetSymbolAddress((void**)&k, g_k);
    cudaGetSymbolAddress((void**)&v, g_v);
    cudaGetSymbolAddress((void**)&pos, g_pos);
    cudaGetSymbolAddress((void**)&rk, g_rk);
    cudaGetSymbolAddress((void**)&logits, g_logits);
    cudaGetSymbolAddress((void**)&o, g_o);
    cudaGetSymbolAddress((void**)&y, g_y);
    cudaGetSymbolAddress((void**)&yn, g_yn);
    cudaGetSymbolAddress((void**)&h1, g_h1);

    // 1) LN1
    ln_kernel<<<Tq, 256>>>(x, ln1_g, ln1_b, xn);
    // 2) fused QKV projections
    qkv_kernel<<<dim3(20, 12), 256>>>(xn, Wq, Wk, Wv, q, k, v);
    // 3) positional features + r_k projection  (M=3071 guarded)
    posfeat_kernel<<<(T2 + 7) / 8, 256>>>(pos);
    sgemm_nn<128><<<dim3(4, 24, 1), 256>>>(pos, FF, 0, Wr, HK, 0, rk, HK, 0,
                                           T2, FF, nullptr, nullptr, 1.f, 0);
    // 4) content logits
    qk128<0><<<dim3(12, 12, NH), 256>>>(q, rwb, k, logits, Tq);
    // 5) relative logits, shifted + accumulated into logits
    qk128<1><<<dim3(24, 12, NH), 256>>>(q, rrb, rk, logits, T2);
    // 6) softmax
    softmax_kernel<<<dim3(Tq, NH), 256>>>(logits);
    // 7) attn @ V (batched over heads, N=192 -> BN=64)
    sgemm_nn<64><<<dim3(3, 12, NH), 256>>>(logits, Tq, (long long)Tq * Tq,
                                           v, HV, VH,
                                           o, HV, VH,
                                           Tq, Tq, nullptr, nullptr, 1.f, 0);
    // 8) output projection + residual
    sgemm_nn<128><<<dim3(12, 12, 1), 256>>>(o, HV, 0, Wo, CC, 0, y, CC, 0,
                                            Tq, HV, bo, x, 1.f, 0);
    // 9) LN2 + MLP
    ln_kernel<<<Tq, 256>>>(y, ln2_g, ln2_b, yn);
    sgemm_nn<128><<<dim3(24, 12, 1), 256>>>(yn, CC, 0, W1, D1, 0, h1, D1, 0,
                                            Tq, CC, b1, nullptr, 1.f, 1);
    sgemm_nn<128><<<dim3(12, 12, 1), 256>>>(h1, D1, 0, W2, CC, 0, out, CC, 0,
                                            Tq, D1, b2, y, 1.f, 0);
}

// round 4
// speedup vs baseline: 2.0769x; 1.5311x over previous
#include <cuda_runtime.h>
#include <cstdint>
#include <math.h>

#define Tq 1536
#define CC 1536
#define T2 3071
#define NH 8
#define KH 64
#define VH 192
#define FF 192
#define HK 512
#define HV 1536
#define D1 3072

// ---------------- helpers ----------------
__device__ __forceinline__ float tf32r(float x) {
    uint32_t u;
    asm("cvt.rna.tf32.f32 %0, %1;" : "=r"(u) : "f"(x));
    return __uint_as_float(u);
}
__device__ __forceinline__ uint32_t smem_u32(const void* p) {
    uint32_t a;
    asm("{ .reg .u64 t; cvta.to.shared.u64 t, %1; cvt.u32.u64 %0, t; }" : "=r"(a) : "l"(p));
    return a;
}
#define CP_ASYNC16(dst, src) \
    asm volatile("cp.async.ca.shared.global [%0], [%1], 16;" :: "r"(dst), "l"(src) : "memory")
#define CP_COMMIT() asm volatile("cp.async.commit_group;" ::: "memory")
#define CP_WAIT(n)  asm volatile("cp.async.wait_group %0;" :: "n"(n) : "memory")

__device__ __forceinline__ void mma8(float* c, const uint32_t* a, const uint32_t* b) {
    asm volatile(
        "mma.sync.aligned.m16n8k8.row.col.f32.tf32.tf32.f32 "
        "{%0,%1,%2,%3}, {%4,%5,%6,%7}, {%8,%9}, {%0,%1,%2,%3};"
        : "+f"(c[0]), "+f"(c[1]), "+f"(c[2]), "+f"(c[3])
        : "r"(a[0]), "r"(a[1]), "r"(a[2]), "r"(a[3]), "r"(b[0]), "r"(b[1]));
}

// ---------------- scratch ----------------
__device__ __align__(128) float g_xn[Tq * CC];
__device__ __align__(128) float g_q[Tq * HK];
__device__ __align__(128) float g_qw[Tq * HK];
__device__ __align__(128) float g_qr[Tq * HK];
__device__ __align__(128) float g_k[Tq * HK];
__device__ __align__(128) float g_vT[HV * Tq];
__device__ __align__(128) float g_pos[(T2 + 1) * FF];
__device__ __align__(128) float g_rk[(T2 + 1) * HK];
__device__ __align__(128) float g_logits[(size_t)NH * Tq * Tq];
__device__ __align__(128) float g_o[Tq * HV];
__device__ __align__(128) float g_y[Tq * CC];
__device__ __align__(128) float g_yn[Tq * CC];
__device__ __align__(128) float g_h1[Tq * D1];
__device__ __align__(128) float g_WqT[HK * CC];
__device__ __align__(128) float g_WkT[HK * CC];
__device__ __align__(128) float g_WvT[HV * CC];
__device__ __align__(128) float g_WrT[HK * FF];
__device__ __align__(128) float g_WoT[CC * HV];
__device__ __align__(128) float g_W1T[D1 * CC];
__device__ __align__(128) float g_W2T[CC * D1];

// ---------------- transpose + tf32 round ----------------
__global__ void transpose_kernel(const float* __restrict__ in, float* __restrict__ out,
                                 int R, int Cc) {
    __shared__ float t[32][33];
    int c0 = blockIdx.x * 32, r0 = blockIdx.y * 32;
    int tx = threadIdx.x, ty = threadIdx.y;   // 32 x 8
#pragma unroll
    for (int i = 0; i < 4; i++)
        t[ty + 8 * i][tx] = in[(size_t)(r0 + ty + 8 * i) * Cc + c0 + tx];
    __syncthreads();
#pragma unroll
    for (int i = 0; i < 4; i++)
        out[(size_t)(c0 + ty + 8 * i) * R + r0 + tx] = tf32r(t[tx][ty + 8 * i]);
}

// ---------------- layernorm (+ tf32 round) ----------------
__global__ void ln_kernel(const float* __restrict__ x, const float* __restrict__ g,
                          const float* __restrict__ b, float* __restrict__ out) {
    int row = blockIdx.x;
    int tid = threadIdx.x;
    const float* xr = x + (size_t)row * CC;
    float v[6];
    float s = 0.f, s2 = 0.f;
#pragma unroll
    for (int e = 0; e < 6; e++) {
        float t = xr[tid + 256 * e];
        v[e] = t; s += t; s2 += t * t;
    }
    __shared__ float sh[16];
#pragma unroll
    for (int o = 16; o > 0; o >>= 1) {
        s  += __shfl_xor_sync(0xffffffffu, s, o);
        s2 += __shfl_xor_sync(0xffffffffu, s2, o);
    }
    int wid = tid >> 5, lane = tid & 31;
    if (lane == 0) { sh[wid] = s; sh[8 + wid] = s2; }
    __syncthreads();
    if (tid == 0) {
        float a = 0.f, c = 0.f;
        for (int i = 0; i < 8; i++) { a += sh[i]; c += sh[8 + i]; }
        sh[0] = a; sh[8] = c;
    }
    __syncthreads();
    float mu  = sh[0] * (1.f / CC);
    float var = sh[8] * (1.f / CC) - mu * mu;
    float rs  = rsqrtf(var + 1e-3f);
#pragma unroll
    for (int e = 0; e < 6; e++) {
        int c = tid + 256 * e;
        out[(size_t)row * CC + c] = tf32r((v[e] - mu) * rs * g[c] + b[c]);
    }
}

// ---------------- q bias: qw = rnd(q + rwb), qr = rnd(q + rrb) ----------------
__global__ void qbias_kernel(const float* __restrict__ q, const float* __restrict__ rwb,
                             const float* __restrict__ rrb,
                             float* __restrict__ qw, float* __restrict__ qr) {
    int idx = blockIdx.x * 256 + threadIdx.x;
    int c = idx & (HK - 1);
    float v = q[idx];
    qw[idx] = tf32r(v + rwb[c]);
    qr[idx] = tf32r(v + rrb[c]);
}

// ---------------- mma.sync tf32 NT GEMM ----------------
// C[M,N] = scale*A@B^T (+bias)(+relu)(+resid); A[M,Kd] lda, B[N,Kd] ldb; batch via z.
// SHIFT=1: C[r, n + r - (Tq-1)] += val
template<int SHIFT>
__global__ void __launch_bounds__(256) mma_gemm(
    const float* __restrict__ A, int lda, long long sA,
    const float* __restrict__ B, int ldb, long long sB,
    float* __restrict__ C, int ldc, long long sC,
    int M, int N, int Kd,
    const float* __restrict__ bias,
    const float* __restrict__ resid,
    float scale, int do_relu, int round_out)
{
    const int row0 = blockIdx.y * 128, col0 = blockIdx.x * 128;
    if constexpr (SHIFT) {
        int jmin = col0 + row0 - (Tq - 1);
        if (jmin + 254 < 0 || jmin > Tq - 1) return;
    }
    __shared__ float sAa[2][128 * 20];
    __shared__ float sBb[2][128 * 20];
    const int tid = threadIdx.x;
    const int wid = tid >> 5, lane = tid & 31;
    const int wr = wid >> 2, wc = wid & 3;
    const long long z = blockIdx.z;
    A += z * sA; B += z * sB; C += z * sC;

    const int r_ld = tid >> 2;               // 0..63 per half
    const int c4 = (tid & 3) * 4;

    auto stage = [&](int kc, int buf) {
        const float* Ak = A + kc * 16;
        const float* Bk = B + kc * 16;
#pragma unroll
        for (int it = 0; it < 2; it++) {
            int r = r_ld + it * 64;
            int ra = row0 + r; if (ra >= M) ra = M - 1;
            uint32_t dst = smem_u32(&sAa[buf][r * 20 + c4]);
            CP_ASYNC16(dst, Ak + (size_t)ra * lda + c4);
        }
#pragma unroll
        for (int it = 0; it < 2; it++) {
            int r = r_ld + it * 64;
            int rb = col0 + r; if (rb >= N) rb = N - 1;
            uint32_t dst = smem_u32(&sBb[buf][r * 20 + c4]);
            CP_ASYNC16(dst, Bk + (size_t)rb * ldb + c4);
        }
    };

    float acc[16][4];
#pragma unroll
    for (int i = 0; i < 16; i++)
#pragma unroll
        for (int j = 0; j < 4; j++) acc[i][j] = 0.f;

    const int nc = Kd >> 4;
    stage(0, 0);
    CP_COMMIT();
    for (int kc = 0; kc < nc; kc++) {
        int buf = kc & 1;
        if (kc + 1 < nc) { stage(kc + 1, buf ^ 1); CP_COMMIT(); CP_WAIT(1); }
        else             { CP_WAIT(0); }
        __syncthreads();
        const float* sA0 = sAa[buf];
        const float* sB0 = sBb[buf];
#pragma unroll
        for (int ks = 0; ks < 2; ks++) {
            int k0 = ks * 8;
            uint32_t a[4][4], b[4][2];
#pragma unroll
            for (int mi = 0; mi < 4; mi++) {
                const float* p = sA0 + (wr * 64 + mi * 16 + (lane >> 2)) * 20 + k0 + (lane & 3);
                a[mi][0] = __float_as_uint(p[0]);
                a[mi][1] = __float_as_uint(p[8 * 20]);
                a[mi][2] = __float_as_uint(p[4]);
                a[mi][3] = __float_as_uint(p[8 * 20 + 4]);
            }
#pragma unroll
            for (int nj = 0; nj < 4; nj++) {
                const float* p = sB0 + (wc * 32 + nj * 8 + (lane >> 2)) * 20 + k0 + (lane & 3);
                b[nj][0] = __float_as_uint(p[0]);
                b[nj][1] = __float_as_uint(p[4]);
            }
#pragma unroll
            for (int mi = 0; mi < 4; mi++)
#pragma unroll
                for (int nj = 0; nj < 4; nj++)
                    mma8(acc[mi * 4 + nj], a[mi], b[nj]);
        }
        __syncthreads();
    }

    // epilogue
#pragma unroll
    for (int mi = 0; mi < 4; mi++) {
#pragma unroll
        for (int half = 0; half < 2; half++) {
            int r = row0 + wr * 64 + mi * 16 + (lane >> 2) + half * 8;
            if (r >= M) continue;
            if constexpr (SHIFT) {
                float* lrow = C + (size_t)r * ldc;
                int shift = r - (Tq - 1);
#pragma unroll
                for (int nj = 0; nj < 4; nj++) {
                    int n = col0 + wc * 32 + nj * 8 + (lane & 3) * 2;
                    float v0 = acc[mi * 4 + nj][half * 2];
                    float v1 = acc[mi * 4 + nj][half * 2 + 1];
                    int j0 = n + shift;
                    if (n < N && j0 >= 0 && j0 < Tq) lrow[j0] += v0;
                    if (n + 1 < N && j0 + 1 >= 0 && j0 + 1 < Tq) lrow[j0 + 1] += v1;
                }
            } else {
                float* crow = C + (size_t)r * ldc;
                const float* rrow = resid ? resid + z * sC + (size_t)r * ldc : nullptr;
#pragma unroll
                for (int nj = 0; nj < 4; nj++) {
                    int cn = col0 + wc * 32 + nj * 8 + (lane & 3) * 2;
                    if (cn >= N) continue;
                    float v0 = acc[mi * 4 + nj][half * 2] * scale;
                    float v1 = acc[mi * 4 + nj][half * 2 + 1] * scale;
                    if (bias) { v0 += bias[cn]; v1 += bias[cn + 1]; }
                    if (do_relu) { v0 = fmaxf(v0, 0.f); v1 = fmaxf(v1, 0.f); }
                    if (rrow) { v0 += rrow[cn]; v1 += rrow[cn + 1]; }
                    if (round_out) { v0 = tf32r(v0); v1 = tf32r(v1); }
                    float2 t = make_float2(v0, v1);
                    *(float2*)(crow + cn) = t;
                }
            }
        }
    }
}

// ---------------- positional features (+round) ----------------
__global__ void posfeat_kernel(float* __restrict__ pos) {
    int warp = threadIdx.x >> 5, lane = threadIdx.x & 31;
    int p = blockIdx.x * 8 + warp;
    if (p >= T2) return;
    float d = (float)(p - (Tq - 1));
    float ap = fabsf(d);
    float sgn = (d > 0.f) ? 1.f : ((d < 0.f) ? -1.f : 0.f);
    double hi = 10.584962500721156;    // log2(1536)
    double exx = 3.0 + (hi - 3.0) * (double)lane / 31.0;
    float half_life = (float)exp2(exx);
    float coef = (float)(-(0.6931471805599453 / (double)half_life));
    float fexp = expf(ap * coef);
    float width = exp2f((float)(lane + 1)) - 1.f;
    float fcm = (width > ap) ? 1.f : 0.f;
    double mean = 48.0 + (1536.0 - 48.0) * (double)lane / 31.0;
    float conc = (float)((mean / 24.0) * (mean / 24.0));
    float rate = (float)(mean / 576.0);
    float log_unnorm = (conc - 1.f) * logf(ap) - rate * ap;
    float log_norm = lgammaf(conc) - conc * logf(rate);
    float prob = expf(log_unnorm - log_norm) + 1e-8f;
    float mx = prob;
#pragma unroll
    for (int o = 16; o > 0; o >>= 1) mx = fmaxf(mx, __shfl_xor_sync(0xffffffffu, mx, o));
    float fg = prob / mx;
    float* row = pos + (size_t)p * FF;
    row[lane]       = tf32r(fexp);
    row[32 + lane]  = tf32r(fcm);
    row[64 + lane]  = tf32r(fg);
    row[96 + lane]  = tf32r(sgn * fexp);
    row[128 + lane] = tf32r(sgn * fcm);
    row[160 + lane] = tf32r(sgn * fg);
}

// ---------------- softmax in place (+round: output feeds tf32 GEMM) ----------------
__global__ void softmax_kernel(float* __restrict__ logits) {
    int q = blockIdx.x, h = blockIdx.y;
    int tid = threadIdx.x;
    float* row = logits + ((size_t)h * Tq + q) * Tq;
    float v[6];
    float mx = -1e30f;
#pragma unroll
    for (int e = 0; e < 6; e++) {
        v[e] = row[tid + 256 * e];
        mx = fmaxf(mx, v[e]);
    }
    __shared__ float sh[8];
#pragma unroll
    for (int o = 16; o > 0; o >>= 1) mx = fmaxf(mx, __shfl_xor_sync(0xffffffffu, mx, o));
    int wid = tid >> 5, lane = tid & 31;
    if (lane == 0) sh[wid] = mx;
    __syncthreads();
    if (tid == 0) { float m = sh[0]; for (int i = 1; i < 8; i++) m = fmaxf(m, sh[i]); sh[0] = m; }
    __syncthreads();
    mx = sh[0];
    __syncthreads();
    float s = 0.f;
#pragma unroll
    for (int e = 0; e < 6; e++) { v[e] = expf(v[e] - mx); s += v[e]; }
#pragma unroll
    for (int o = 16; o > 0; o >>= 1) s += __shfl_xor_sync(0xffffffffu, s, o);
    if (lane == 0) sh[wid] = s;
    __syncthreads();
    if (tid == 0) { float m = 0.f; for (int i = 0; i < 8; i++) m += sh[i]; sh[0] = m; }
    __syncthreads();
    float inv = 1.f / sh[0];
#pragma unroll
    for (int e = 0; e < 6; e++) row[tid + 256 * e] = tf32r(v[e] * inv);
}

// ---------------- host ----------------
extern "C" void kernel_launch(void* const* d_in, const int* in_sizes, int n_in,
                              void* d_out, int out_size) {
    (void)in_sizes; (void)n_in; (void)out_size;
    const float* x     = (const float*)d_in[0];
    const float* ln1_g = (const float*)d_in[1];
    const float* ln1_b = (const float*)d_in[2];
    const float* ln2_g = (const float*)d_in[3];
    const float* ln2_b = (const float*)d_in[4];
    const float* Wq    = (const float*)d_in[5];
    const float* Wk    = (const float*)d_in[6];
    const float* Wv    = (const float*)d_in[7];
    const float* Wr    = (const float*)d_in[8];
    const float* Wo    = (const float*)d_in[9];
    const float* bo    = (const float*)d_in[10];
    const float* rwb   = (const float*)d_in[11];
    const float* rrb   = (const float*)d_in[12];
    const float* W1    = (const float*)d_in[13];
    const float* b1    = (const float*)d_in[14];
    const float* W2    = (const float*)d_in[15];
    const float* b2    = (const float*)d_in[16];
    float* out = (float*)d_out;

    float *xn, *q, *qw, *qr, *k, *vT, *pos, *rk, *logits, *o, *y, *yn, *h1;
    float *WqT, *WkT, *WvT, *WrT, *WoT, *W1T, *W2T;
    cudaGetSymbolAddress((void**)&xn, g_xn);
    cudaGetSymbolAddress((void**)&q, g_q);
    cudaGetSymbolAddress((void**)&qw, g_qw);
    cudaGetSymbolAddress((void**)&qr, g_qr);
    cudaGetSymbolAddress((void**)&k, g_k);
    cudaGetSymbolAddress((void**)&vT, g_vT);
    cudaGetSymbolAddress((void**)&pos, g_pos);
    cudaGetSymbolAddress((void**)&rk, g_rk);
    cudaGetSymbolAddress((void**)&logits, g_logits);
    cudaGetSymbolAddress((void**)&o, g_o);
    cudaGetSymbolAddress((void**)&y, g_y);
    cudaGetSymbolAddress((void**)&yn, g_yn);
    cudaGetSymbolAddress((void**)&h1, g_h1);
    cudaGetSymbolAddress((void**)&WqT, g_WqT);
    cudaGetSymbolAddress((void**)&WkT, g_WkT);
    cudaGetSymbolAddress((void**)&WvT, g_WvT);
    cudaGetSymbolAddress((void**)&WrT, g_WrT);
    cudaGetSymbolAddress((void**)&WoT, g_WoT);
    cudaGetSymbolAddress((void**)&W1T, g_W1T);
    cudaGetSymbolAddress((void**)&W2T, g_W2T);

    dim3 tb(32, 8);
    transpose_kernel<<<dim3(HK / 32, CC / 32), tb>>>(Wq, WqT, CC, HK);
    transpose_kernel<<<dim3(HK / 32, CC / 32), tb>>>(Wk, WkT, CC, HK);
    transpose_kernel<<<dim3(HV / 32, CC / 32), tb>>>(Wv, WvT, CC, HV);
    transpose_kernel<<<dim3(HK / 32, FF / 32), tb>>>(Wr, WrT, FF, HK);
    transpose_kernel<<<dim3(CC / 32, HV / 32), tb>>>(Wo, WoT, HV, CC);
    transpose_kernel<<<dim3(D1 / 32, CC / 32), tb>>>(W1, W1T, CC, D1);
    transpose_kernel<<<dim3(CC / 32, D1 / 32), tb>>>(W2, W2T, D1, CC);

    // LN1 (tf32-rounded output)
    ln_kernel<<<Tq, 256>>>(x, ln1_g, ln1_b, xn);
    // q (scaled, unrounded), k (rounded)
    mma_gemm<0><<<dim3(HK / 128, Tq / 128), 256>>>(
        xn, CC, 0, WqT, CC, 0, q, HK, 0, Tq, HK, CC, nullptr, nullptr, 0.125f, 0, 0);
    mma_gemm<0><<<dim3(HK / 128, Tq / 128), 256>>>(
        xn, CC, 0, WkT, CC, 0, k, HK, 0, Tq, HK, CC, nullptr, nullptr, 1.f, 0, 1);
    // vT = WvT @ xn^T (rounded)
    mma_gemm<0><<<dim3(Tq / 128, HV / 128), 256>>>(
        WvT, CC, 0, xn, CC, 0, vT, Tq, 0, HV, Tq, CC, nullptr, nullptr, 1.f, 0, 1);
    // qw/qr
    qbias_kernel<<<Tq * HK / 256, 256>>>(q, rwb, rrb, qw, qr);
    // positional features + rk (rounded)
    posfeat_kernel<<<(T2 + 7) / 8, 256>>>(pos);
    mma_gemm<0><<<dim3(HK / 128, (T2 + 127) / 128), 256>>>(
        pos, FF, 0, WrT, FF, 0, rk, HK, 0, T2, HK, FF, nullptr, nullptr, 1.f, 0, 1);
    // content logits
    mma_gemm<0><<<dim3(Tq / 128, Tq / 128, NH), 256>>>(
        qw, HK, KH, k, HK, KH, logits, Tq, (long long)Tq * Tq,
        Tq, Tq, KH, nullptr, nullptr, 1.f, 0, 0);
    // rel logits shifted into logits
    mma_gemm<1><<<dim3((T2 + 127) / 128, Tq / 128, NH), 256>>>(
        qr, HK, KH, rk, HK, KH, logits, Tq, (long long)Tq * Tq,
        Tq, T2, KH, nullptr, nullptr, 1.f, 0, 0);
    // softmax (tf32-rounded probs)
    softmax_kernel<<<dim3(Tq, NH), 256>>>(logits);
    // o = probs @ v (rounded)
    mma_gemm<0><<<dim3(2, Tq / 128, NH), 256>>>(
        logits, Tq, (long long)Tq * Tq, vT, Tq, (long long)VH * Tq,
        o, HV, VH, Tq, VH, Tq, nullptr, nullptr, 1.f, 0, 1);
    // y = x + o @ Wo + bo (fp32)
    mma_gemm<0><<<dim3(CC / 128, Tq / 128), 256>>>(
        o, HV, 0, WoT, HV, 0, y, CC, 0, Tq, CC, HV, bo, x, 1.f, 0, 0);
    // LN2 + MLP
    ln_kernel<<<Tq, 256>>>(y, ln2_g, ln2_b, yn);
    mma_gemm<0><<<dim3(D1 / 128, Tq / 128), 256>>>(
        yn, CC, 0, W1T, CC, 0, h1, D1, 0, Tq, D1, CC, b1, nullptr, 1.f, 1, 1);
    mma_gemm<0><<<dim3(CC / 128, Tq / 128), 256>>>(
        h1, D1, 0, W2T, D1, 0, out, CC, 0, Tq, CC, D1, b2, y, 1.f, 0, 0);
}

// round 5
// speedup vs baseline: 3.6856x; 1.7746x over previous
#include <cuda_runtime.h>
#include <cuda_fp16.h>
#include <cstdint>
#include <math.h>

#define Tq 1536
#define CC 1536
#define T2 3071
#define NH 8
#define KH 64
#define VH 192
#define FF 192
#define HK 512
#define HV 1536
#define D1 3072

// ---------------- PTX helpers ----------------
__device__ __forceinline__ uint32_t smem_u32(const void* p) {
    uint32_t a;
    asm("{ .reg .u64 t; cvta.to.shared.u64 t, %1; cvt.u32.u64 %0, t; }" : "=r"(a) : "l"(p));
    return a;
}
#define CP_ASYNC16(dst, src) \
    asm volatile("cp.async.ca.shared.global [%0], [%1], 16;" :: "r"(dst), "l"(src) : "memory")
#define CP_COMMIT() asm volatile("cp.async.commit_group;" ::: "memory")
#define CP_WAIT(n)  asm volatile("cp.async.wait_group %0;" :: "n"(n) : "memory")
#define LDSM4(r0, r1, r2, r3, addr) \
    asm volatile("ldmatrix.sync.aligned.m8n8.x4.shared.b16 {%0,%1,%2,%3}, [%4];" \
        : "=r"(r0), "=r"(r1), "=r"(r2), "=r"(r3) : "r"(addr))

__device__ __forceinline__ void mma16(float* c, const uint32_t* a, const uint32_t* b) {
    asm volatile(
        "mma.sync.aligned.m16n8k16.row.col.f32.f16.f16.f32 "
        "{%0,%1,%2,%3}, {%4,%5,%6,%7}, {%8,%9}, {%0,%1,%2,%3};"
        : "+f"(c[0]), "+f"(c[1]), "+f"(c[2]), "+f"(c[3])
        : "r"(a[0]), "r"(a[1]), "r"(a[2]), "r"(a[3]), "r"(b[0]), "r"(b[1]));
}

// ---------------- scratch ----------------
__device__ __align__(128) float  g_logits[(size_t)NH * Tq * Tq];
__device__ __align__(128) float  g_y[Tq * CC];
__device__ __align__(128) __half h_xn[Tq * CC];
__device__ __align__(128) __half h_qw[Tq * HK];
__device__ __align__(128) __half h_qr[Tq * HK];
__device__ __align__(128) __half h_k[Tq * HK];
__device__ __align__(128) __half h_vT[HV * Tq];
__device__ __align__(128) __half h_pos[(T2 + 1) * FF];
__device__ __align__(128) __half h_rk[(T2 + 1) * HK];
__device__ __align__(128) __half h_probs[(size_t)NH * Tq * Tq];
__device__ __align__(128) __half h_o[Tq * HV];
__device__ __align__(128) __half h_yn[Tq * CC];
__device__ __align__(128) __half h_h1[Tq * D1];
__device__ __align__(128) __half h_WqkT[(HK * 2) * CC];
__device__ __align__(128) __half h_WvT[HV * CC];
__device__ __align__(128) __half h_WrT[HK * FF];
__device__ __align__(128) __half h_WoT[CC * HV];
__device__ __align__(128) __half h_W1T[D1 * CC];
__device__ __align__(128) __half h_W2T[CC * D1];

// ---------------- transpose fp32 -> fp16, optional scale ----------------
__global__ void transpose_kernel(const float* __restrict__ in, __half* __restrict__ out,
                                 int R, int Cc, float scale) {
    __shared__ float t[32][33];
    int c0 = blockIdx.x * 32, r0 = blockIdx.y * 32;
    int tx = threadIdx.x, ty = threadIdx.y;   // 32 x 8
#pragma unroll
    for (int i = 0; i < 4; i++)
        t[ty + 8 * i][tx] = in[(size_t)(r0 + ty + 8 * i) * Cc + c0 + tx];
    __syncthreads();
#pragma unroll
    for (int i = 0; i < 4; i++)
        out[(size_t)(c0 + ty + 8 * i) * R + r0 + tx] = __float2half_rn(t[tx][ty + 8 * i] * scale);
}

// ---------------- layernorm fp32 -> fp16 ----------------
__global__ void ln_kernel(const float* __restrict__ x, const float* __restrict__ g,
                          const float* __restrict__ b, __half* __restrict__ out) {
    int row = blockIdx.x;
    int tid = threadIdx.x;
    const float* xr = x + (size_t)row * CC;
    float v[6];
    float s = 0.f, s2 = 0.f;
#pragma unroll
    for (int e = 0; e < 6; e++) {
        float t = xr[tid + 256 * e];
        v[e] = t; s += t; s2 += t * t;
    }
    __shared__ float sh[16];
#pragma unroll
    for (int o = 16; o > 0; o >>= 1) {
        s  += __shfl_xor_sync(0xffffffffu, s, o);
        s2 += __shfl_xor_sync(0xffffffffu, s2, o);
    }
    int wid = tid >> 5, lane = tid & 31;
    if (lane == 0) { sh[wid] = s; sh[8 + wid] = s2; }
    __syncthreads();
    if (tid == 0) {
        float a = 0.f, c = 0.f;
        for (int i = 0; i < 8; i++) { a += sh[i]; c += sh[8 + i]; }
        sh[0] = a; sh[8] = c;
    }
    __syncthreads();
    float mu  = sh[0] * (1.f / CC);
    float var = sh[8] * (1.f / CC) - mu * mu;
    float rs  = rsqrtf(var + 1e-3f);
#pragma unroll
    for (int e = 0; e < 6; e++) {
        int c = tid + 256 * e;
        out[(size_t)row * CC + c] = __float2half_rn((v[e] - mu) * rs * g[c] + b[c]);
    }
}

// ---------------- fp16 mma NT GEMM: C = A @ B^T ----------------
// A [M,Kd] K-major halves, B [N,Kd] K-major halves. BM=BN=128, BK=64, 8 warps (2x4).
// MODE 0: fp32 out (+bias)(+resid)   MODE 1: fp16 out (+bias)(+relu)
// MODE 2: shift scatter RMW into fp32 logits    MODE 3: fused QK epilogue
template<int MODE>
__global__ void __launch_bounds__(256, 2) mma_gemm(
    const __half* __restrict__ A, int lda, long long strA,
    const __half* __restrict__ B, int ldb, long long strB,
    void* __restrict__ Cv, int ldc, long long strC,
    int M, int N, int Kd,
    const float* __restrict__ bias,
    const float* __restrict__ resid,
    int do_relu)
{
    const int row0 = blockIdx.y * 128, col0 = blockIdx.x * 128;
    if constexpr (MODE == 2) {
        int jmin = col0 + row0 - (Tq - 1);
        if (jmin + 254 < 0 || jmin > Tq - 1) return;
    }
    extern __shared__ char smem[];
    const int tid = threadIdx.x;
    const int wid = tid >> 5, lane = tid & 31;
    const int wr = wid >> 2, wc = wid & 3;
    const long long z = blockIdx.z;
    A += z * strA; B += z * strB;

    auto stage = [&](int kc, int buf) {
        const __half* Ak = A + (size_t)kc * 64;
        const __half* Bk = B + (size_t)kc * 64;
        char* sAb = smem + buf * 16384;
        char* sBb = smem + 32768 + buf * 16384;
#pragma unroll
        for (int it = 0; it < 4; it++) {
            int linear = tid + it * 256;
            int r = linear >> 3, g = linear & 7;
            int ra = row0 + r; if (ra >= M) ra = M - 1;
            uint32_t dst = smem_u32(sAb + r * 128 + ((g ^ (r & 7)) << 4));
            CP_ASYNC16(dst, Ak + (size_t)ra * lda + g * 8);
        }
#pragma unroll
        for (int it = 0; it < 4; it++) {
            int linear = tid + it * 256;
            int r = linear >> 3, g = linear & 7;
            int rb = col0 + r; if (rb >= N) rb = N - 1;
            uint32_t dst = smem_u32(sBb + r * 128 + ((g ^ (r & 7)) << 4));
            CP_ASYNC16(dst, Bk + (size_t)rb * ldb + g * 8);
        }
    };

    float acc[16][4] = {};
    const int nc = Kd >> 6;
    stage(0, 0);
    CP_COMMIT();
    for (int kc = 0; kc < nc; kc++) {
        int buf = kc & 1;
        if (kc + 1 < nc) { stage(kc + 1, buf ^ 1); CP_COMMIT(); CP_WAIT(1); }
        else             { CP_WAIT(0); }
        __syncthreads();
        const char* sAb = smem + buf * 16384;
        const char* sBb = smem + 32768 + buf * 16384;
#pragma unroll
        for (int ks = 0; ks < 4; ks++) {
            int gb = ks * 2 + (lane >> 4);
            uint32_t a[4][4], bfr[4][2];
#pragma unroll
            for (int mi = 0; mi < 4; mi++) {
                int r = wr * 64 + mi * 16 + (lane & 15);
                uint32_t ad = smem_u32(sAb + r * 128 + ((gb ^ (r & 7)) << 4));
                LDSM4(a[mi][0], a[mi][1], a[mi][2], a[mi][3], ad);
            }
#pragma unroll
            for (int nb = 0; nb < 2; nb++) {
                int n = wc * 32 + nb * 16 + (lane & 15);
                uint32_t ad = smem_u32(sBb + n * 128 + ((gb ^ (n & 7)) << 4));
                uint32_t q0, q1, q2, q3;
                LDSM4(q0, q1, q2, q3, ad);
                bfr[nb * 2][0] = q0;     bfr[nb * 2][1] = q2;
                bfr[nb * 2 + 1][0] = q1; bfr[nb * 2 + 1][1] = q3;
            }
#pragma unroll
            for (int mi = 0; mi < 4; mi++)
#pragma unroll
                for (int nj = 0; nj < 4; nj++)
                    mma16(acc[mi * 4 + nj], a[mi], bfr[nj]);
        }
        __syncthreads();
    }

    // epilogue
#pragma unroll
    for (int mi = 0; mi < 4; mi++) {
#pragma unroll
        for (int hf = 0; hf < 2; hf++) {
            int r = row0 + wr * 64 + mi * 16 + (lane >> 2) + hf * 8;
            if (r >= M) continue;
#pragma unroll
            for (int nj = 0; nj < 4; nj++) {
                int cn = col0 + wc * 32 + nj * 8 + (lane & 3) * 2;
                float v0 = acc[mi * 4 + nj][hf * 2];
                float v1 = acc[mi * 4 + nj][hf * 2 + 1];
                if constexpr (MODE == 0) {
                    if (cn >= N) continue;
                    float* C = (float*)Cv + z * strC;
                    if (bias) { v0 += bias[cn]; v1 += bias[cn + 1]; }
                    if (resid) {
                        v0 += resid[(size_t)r * ldc + cn];
                        v1 += resid[(size_t)r * ldc + cn + 1];
                    }
                    *(float2*)(C + (size_t)r * ldc + cn) = make_float2(v0, v1);
                } else if constexpr (MODE == 1) {
                    if (cn >= N) continue;
                    __half* C = (__half*)Cv + z * strC;
                    if (bias) { v0 += bias[cn]; v1 += bias[cn + 1]; }
                    if (do_relu) { v0 = fmaxf(v0, 0.f); v1 = fmaxf(v1, 0.f); }
                    __half2 t;
                    t.x = __float2half_rn(v0); t.y = __float2half_rn(v1);
                    *(__half2*)(C + (size_t)r * ldc + cn) = t;
                } else if constexpr (MODE == 2) {
                    float* lrow = (float*)Cv + z * strC + (size_t)r * ldc;
                    int j0 = cn + r - (Tq - 1);
                    if (cn < N && j0 >= 0 && j0 < Tq) lrow[j0] += v0;
                    if (cn + 1 < N && j0 + 1 >= 0 && j0 + 1 < Tq) lrow[j0 + 1] += v1;
                } else {  // MODE 3: fused QK
                    if (cn < HK) {
                        __half2 tw, tr;
                        tw.x = __float2half_rn(v0 + bias[cn]);
                        tw.y = __float2half_rn(v1 + bias[cn + 1]);
                        tr.x = __float2half_rn(v0 + resid[cn]);
                        tr.y = __float2half_rn(v1 + resid[cn + 1]);
                        *(__half2*)(h_qw + (size_t)r * HK + cn) = tw;
                        *(__half2*)(h_qr + (size_t)r * HK + cn) = tr;
                    } else {
                        __half2 tk;
                        tk.x = __float2half_rn(v0); tk.y = __float2half_rn(v1);
                        *(__half2*)(h_k + (size_t)r * HK + cn - HK) = tk;
                    }
                }
            }
        }
    }
}

// ---------------- positional features -> fp16 ----------------
__global__ void posfeat_kernel(__half* __restrict__ pos) {
    int warp = threadIdx.x >> 5, lane = threadIdx.x & 31;
    int p = blockIdx.x * 8 + warp;
    if (p >= T2) return;
    float d = (float)(p - (Tq - 1));
    float ap = fabsf(d);
    float sgn = (d > 0.f) ? 1.f : ((d < 0.f) ? -1.f : 0.f);
    double hi = 10.584962500721156;    // log2(1536)
    double exx = 3.0 + (hi - 3.0) * (double)lane / 31.0;
    float half_life = (float)exp2(exx);
    float coef = (float)(-(0.6931471805599453 / (double)half_life));
    float fexp = expf(ap * coef);
    float width = exp2f((float)(lane + 1)) - 1.f;
    float fcm = (width > ap) ? 1.f : 0.f;
    double mean = 48.0 + (1536.0 - 48.0) * (double)lane / 31.0;
    float conc = (float)((mean / 24.0) * (mean / 24.0));
    float rate = (float)(mean / 576.0);
    float log_unnorm = (conc - 1.f) * logf(ap) - rate * ap;
    float log_norm = lgammaf(conc) - conc * logf(rate);
    float prob = expf(log_unnorm - log_norm) + 1e-8f;
    float mx = prob;
#pragma unroll
    for (int o = 16; o > 0; o >>= 1) mx = fmaxf(mx, __shfl_xor_sync(0xffffffffu, mx, o));
    float fg = prob / mx;
    __half* row = pos + (size_t)p * FF;
    row[lane]       = __float2half_rn(fexp);
    row[32 + lane]  = __float2half_rn(fcm);
    row[64 + lane]  = __float2half_rn(fg);
    row[96 + lane]  = __float2half_rn(sgn * fexp);
    row[128 + lane] = __float2half_rn(sgn * fcm);
    row[160 + lane] = __float2half_rn(sgn * fg);
}

// ---------------- softmax: fp32 logits -> fp16 probs ----------------
__global__ void softmax_kernel(const float* __restrict__ logits, __half* __restrict__ probs) {
    int q = blockIdx.x, h = blockIdx.y;
    int tid = threadIdx.x;
    const float* row = logits + ((size_t)h * Tq + q) * Tq;
    __half* prow = probs + ((size_t)h * Tq + q) * Tq;
    float v[6];
    float mx = -1e30f;
#pragma unroll
    for (int e = 0; e < 6; e++) {
        v[e] = row[tid + 256 * e];
        mx = fmaxf(mx, v[e]);
    }
    __shared__ float sh[8];
#pragma unroll
    for (int o = 16; o > 0; o >>= 1) mx = fmaxf(mx, __shfl_xor_sync(0xffffffffu, mx, o));
    int wid = tid >> 5, lane = tid & 31;
    if (lane == 0) sh[wid] = mx;
    __syncthreads();
    if (tid == 0) { float m = sh[0]; for (int i = 1; i < 8; i++) m = fmaxf(m, sh[i]); sh[0] = m; }
    __syncthreads();
    mx = sh[0];
    __syncthreads();
    float s = 0.f;
#pragma unroll
    for (int e = 0; e < 6; e++) { v[e] = expf(v[e] - mx); s += v[e]; }
#pragma unroll
    for (int o = 16; o > 0; o >>= 1) s += __shfl_xor_sync(0xffffffffu, s, o);
    if (lane == 0) sh[wid] = s;
    __syncthreads();
    if (tid == 0) { float m = 0.f; for (int i = 0; i < 8; i++) m += sh[i]; sh[0] = m; }
    __syncthreads();
    float inv = 1.f / sh[0];
#pragma unroll
    for (int e = 0; e < 6; e++) prow[tid + 256 * e] = __float2half_rn(v[e] * inv);
}

// ---------------- host ----------------
#define GSMEM 65536

extern "C" void kernel_launch(void* const* d_in, const int* in_sizes, int n_in,
                              void* d_out, int out_size) {
    (void)in_sizes; (void)n_in; (void)out_size;
    const float* x     = (const float*)d_in[0];
    const float* ln1_g = (const float*)d_in[1];
    const float* ln1_b = (const float*)d_in[2];
    const float* ln2_g = (const float*)d_in[3];
    const float* ln2_b = (const float*)d_in[4];
    const float* Wq    = (const float*)d_in[5];
    const float* Wk    = (const float*)d_in[6];
    const float* Wv    = (const float*)d_in[7];
    const float* Wr    = (const float*)d_in[8];
    const float* Wo    = (const float*)d_in[9];
    const float* bo    = (const float*)d_in[10];
    const float* rwb   = (const float*)d_in[11];
    const float* rrb   = (const float*)d_in[12];
    const float* W1    = (const float*)d_in[13];
    const float* b1    = (const float*)d_in[14];
    const float* W2    = (const float*)d_in[15];
    const float* b2    = (const float*)d_in[16];
    float* out = (float*)d_out;

    cudaFuncSetAttribute(mma_gemm<0>, cudaFuncAttributeMaxDynamicSharedMemorySize, GSMEM);
    cudaFuncSetAttribute(mma_gemm<1>, cudaFuncAttributeMaxDynamicSharedMemorySize, GSMEM);
    cudaFuncSetAttribute(mma_gemm<2>, cudaFuncAttributeMaxDynamicSharedMemorySize, GSMEM);
    cudaFuncSetAttribute(mma_gemm<3>, cudaFuncAttributeMaxDynamicSharedMemorySize, GSMEM);

    float *logits, *y;
    __half *xn, *qw, *qr, *k, *vT, *pos, *rk, *probs, *o, *yn, *h1;
    __half *WqkT, *WvT, *WrT, *WoT, *W1T, *W2T;
    cudaGetSymbolAddress((void**)&logits, g_logits);
    cudaGetSymbolAddress((void**)&y, g_y);
    cudaGetSymbolAddress((void**)&xn, h_xn);
    cudaGetSymbolAddress((void**)&qw, h_qw);
    cudaGetSymbolAddress((void**)&qr, h_qr);
    cudaGetSymbolAddress((void**)&k, h_k);
    cudaGetSymbolAddress((void**)&vT, h_vT);
    cudaGetSymbolAddress((void**)&pos, h_pos);
    cudaGetSymbolAddress((void**)&rk, h_rk);
    cudaGetSymbolAddress((void**)&probs, h_probs);
    cudaGetSymbolAddress((void**)&o, h_o);
    cudaGetSymbolAddress((void**)&yn, h_yn);
    cudaGetSymbolAddress((void**)&h1, h_h1);
    cudaGetSymbolAddress((void**)&WqkT, h_WqkT);
    cudaGetSymbolAddress((void**)&WvT, h_WvT);
    cudaGetSymbolAddress((void**)&WrT, h_WrT);
    cudaGetSymbolAddress((void**)&WoT, h_WoT);
    cudaGetSymbolAddress((void**)&W1T, h_W1T);
    cudaGetSymbolAddress((void**)&W2T, h_W2T);

    dim3 tb(32, 8);
    transpose_kernel<<<dim3(HK / 32, CC / 32), tb>>>(Wq, WqkT, CC, HK, 0.125f);
    transpose_kernel<<<dim3(HK / 32, CC / 32), tb>>>(Wk, WqkT + (size_t)HK * CC, CC, HK, 1.f);
    transpose_kernel<<<dim3(HV / 32, CC / 32), tb>>>(Wv, WvT, CC, HV, 1.f);
    transpose_kernel<<<dim3(HK / 32, FF / 32), tb>>>(Wr, WrT, FF, HK, 1.f);
    transpose_kernel<<<dim3(CC / 32, HV / 32), tb>>>(Wo, WoT, HV, CC, 1.f);
    transpose_kernel<<<dim3(D1 / 32, CC / 32), tb>>>(W1, W1T, CC, D1, 1.f);
    transpose_kernel<<<dim3(CC / 32, D1 / 32), tb>>>(W2, W2T, D1, CC, 1.f);

    // LN1
    ln_kernel<<<Tq, 256>>>(x, ln1_g, ln1_b, xn);
    // fused QK: writes qw, qr, k (scale folded into WqT)
    mma_gemm<3><<<dim3(8, 12), 256, GSMEM>>>(
        xn, CC, 0, WqkT, CC, 0, nullptr, 0, 0, Tq, HK * 2, CC, rwb, rrb, 0);
    // vT = WvT @ xn^T
    mma_gemm<1><<<dim3(12, 12), 256, GSMEM>>>(
        WvT, CC, 0, xn, CC, 0, vT, Tq, 0, HV, Tq, CC, nullptr, nullptr, 0);
    // positional features + rk
    posfeat_kernel<<<(T2 + 7) / 8, 256>>>(pos);
    mma_gemm<1><<<dim3(4, 24), 256, GSMEM>>>(
        pos, FF, 0, WrT, FF, 0, rk, HK, 0, T2, HK, FF, nullptr, nullptr, 0);
    // content logits
    mma_gemm<0><<<dim3(12, 12, NH), 256, GSMEM>>>(
        qw, HK, KH, k, HK, KH, logits, Tq, (long long)Tq * Tq,
        Tq, Tq, KH, nullptr, nullptr, 0);
    // rel logits shifted into logits
    mma_gemm<2><<<dim3(24, 12, NH), 256, GSMEM>>>(
        qr, HK, KH, rk, HK, KH, logits, Tq, (long long)Tq * Tq,
        Tq, T2, KH, nullptr, nullptr, 0);
    // softmax -> half probs
    softmax_kernel<<<dim3(Tq, NH), 256>>>(logits, probs);
    // o = probs @ v
    mma_gemm<1><<<dim3(2, 12, NH), 256, GSMEM>>>(
        probs, Tq, (long long)Tq * Tq, vT, Tq, (long long)VH * Tq,
        o, HV, VH, Tq, VH, Tq, nullptr, nullptr, 0);
    // y = x + o @ Wo + bo
    mma_gemm<0><<<dim3(12, 12), 256, GSMEM>>>(
        o, HV, 0, WoT, HV, 0, y, CC, 0, Tq, CC, HV, bo, x, 0);
    // LN2 + MLP
    ln_kernel<<<Tq, 256>>>(y, ln2_g, ln2_b, yn);
    mma_gemm<1><<<dim3(24, 12), 256, GSMEM>>>(
        yn, CC, 0, W1T, CC, 0, h1, D1, 0, Tq, D1, CC, b1, nullptr, 1);
    mma_gemm<0><<<dim3(12, 12), 256, GSMEM>>>(
        h1, D1, 0, W2T, D1, 0, out, CC, 0, Tq, CC, D1, b2, y, 0);
}

// round 6
// speedup vs baseline: 5.8636x; 1.5910x over previous
#include <cuda_runtime.h>
#include <cuda_fp16.h>
#include <cstdint>
#include <math.h>

#define Tq 1536
#define CC 1536
#define T2 3071
#define NH 8
#define KH 64
#define VH 192
#define FF 192
#define HK 512
#define HV 1536
#define D1 3072

// ---------------- PTX helpers ----------------
__device__ __forceinline__ uint32_t smem_u32(const void* p) {
    uint32_t a;
    asm("{ .reg .u64 t; cvta.to.shared.u64 t, %1; cvt.u32.u64 %0, t; }" : "=r"(a) : "l"(p));
    return a;
}
#define CP_ASYNC16(dst, src) \
    asm volatile("cp.async.ca.shared.global [%0], [%1], 16;" :: "r"(dst), "l"(src) : "memory")
#define CP_COMMIT() asm volatile("cp.async.commit_group;" ::: "memory")
#define CP_WAIT(n)  asm volatile("cp.async.wait_group %0;" :: "n"(n) : "memory")
#define LDSM4(r0, r1, r2, r3, addr) \
    asm volatile("ldmatrix.sync.aligned.m8n8.x4.shared.b16 {%0,%1,%2,%3}, [%4];" \
        : "=r"(r0), "=r"(r1), "=r"(r2), "=r"(r3) : "r"(addr))

__device__ __forceinline__ void mma16(float* c, const uint32_t* a, const uint32_t* b) {
    asm volatile(
        "mma.sync.aligned.m16n8k16.row.col.f32.f16.f16.f32 "
        "{%0,%1,%2,%3}, {%4,%5,%6,%7}, {%8,%9}, {%0,%1,%2,%3};"
        : "+f"(c[0]), "+f"(c[1]), "+f"(c[2]), "+f"(c[3])
        : "r"(a[0]), "r"(a[1]), "r"(a[2]), "r"(a[3]), "r"(b[0]), "r"(b[1]));
}

// ---------------- scratch ----------------
__device__ __align__(128) float  g_logits[(size_t)NH * Tq * Tq];
__device__ __align__(128) float  g_y[Tq * CC];
__device__ __align__(128) __half h_xn[Tq * CC];
__device__ __align__(128) __half h_qw[Tq * HK];
__device__ __align__(128) __half h_qr[Tq * HK];
__device__ __align__(128) __half h_k[Tq * HK];
__device__ __align__(128) __half h_vT[HV * Tq];
__device__ __align__(128) __half h_pos[(T2 + 1) * FF];
__device__ __align__(128) __half h_rk[(T2 + 1) * HK];
__device__ __align__(128) __half h_probs[(size_t)NH * Tq * Tq];
__device__ __align__(128) __half h_o[Tq * HV];
__device__ __align__(128) __half h_yn[Tq * CC];
__device__ __align__(128) __half h_h1[Tq * D1];
__device__ __align__(128) __half h_WqkT[(HK * 2) * CC];
__device__ __align__(128) __half h_WvT[HV * CC];
__device__ __align__(128) __half h_WrT[HK * FF];
__device__ __align__(128) __half h_WoT[CC * HV];
__device__ __align__(128) __half h_W1T[D1 * CC];
__device__ __align__(128) __half h_W2T[CC * D1];

// ---------------- merged transpose: all 7 weights in one launch ----------------
__global__ void transpose_all(const float* __restrict__ Wq, const float* __restrict__ Wk,
                              const float* __restrict__ Wv, const float* __restrict__ Wr,
                              const float* __restrict__ Wo, const float* __restrict__ W1,
                              const float* __restrict__ W2) {
    int b = blockIdx.x;
    const float* in; __half* out; int Rr, Cc, bx, by; float scale = 1.f;
    if (b < 768)        { in = Wq; out = h_WqkT; Rr = CC; Cc = HK; scale = 0.125f; bx = b % 16; by = b / 16; }
    else if (b < 1536)  { b -= 768;  in = Wk; out = h_WqkT + (size_t)HK * CC; Rr = CC; Cc = HK; bx = b % 16; by = b / 16; }
    else if (b < 3840)  { b -= 1536; in = Wv; out = h_WvT; Rr = CC; Cc = HV; bx = b % 48; by = b / 48; }
    else if (b < 3936)  { b -= 3840; in = Wr; out = h_WrT; Rr = FF; Cc = HK; bx = b % 16; by = b / 16; }
    else if (b < 6240)  { b -= 3936; in = Wo; out = h_WoT; Rr = HV; Cc = CC; bx = b % 48; by = b / 48; }
    else if (b < 10848) { b -= 6240; in = W1; out = h_W1T; Rr = CC; Cc = D1; bx = b % 96; by = b / 96; }
    else                { b -= 10848; in = W2; out = h_W2T; Rr = D1; Cc = CC; bx = b % 48; by = b / 48; }
    __shared__ float t[32][33];
    int c0 = bx * 32, r0 = by * 32;
    int tx = threadIdx.x, ty = threadIdx.y;   // 32 x 8
#pragma unroll
    for (int i = 0; i < 4; i++)
        t[ty + 8 * i][tx] = in[(size_t)(r0 + ty + 8 * i) * Cc + c0 + tx];
    __syncthreads();
#pragma unroll
    for (int i = 0; i < 4; i++)
        out[(size_t)(c0 + ty + 8 * i) * Rr + r0 + tx] = __float2half_rn(t[tx][ty + 8 * i] * scale);
}

// ---------------- layernorm fp32 -> fp16 ----------------
__global__ void ln_kernel(const float* __restrict__ x, const float* __restrict__ g,
                          const float* __restrict__ b, __half* __restrict__ out) {
    int row = blockIdx.x;
    int tid = threadIdx.x;
    const float* xr = x + (size_t)row * CC;
    float v[6];
    float s = 0.f, s2 = 0.f;
#pragma unroll
    for (int e = 0; e < 6; e++) {
        float t = xr[tid + 256 * e];
        v[e] = t; s += t; s2 += t * t;
    }
    __shared__ float sh[16];
#pragma unroll
    for (int o = 16; o > 0; o >>= 1) {
        s  += __shfl_xor_sync(0xffffffffu, s, o);
        s2 += __shfl_xor_sync(0xffffffffu, s2, o);
    }
    int wid = tid >> 5, lane = tid & 31;
    if (lane == 0) { sh[wid] = s; sh[8 + wid] = s2; }
    __syncthreads();
    if (tid == 0) {
        float a = 0.f, c = 0.f;
        for (int i = 0; i < 8; i++) { a += sh[i]; c += sh[8 + i]; }
        sh[0] = a; sh[8] = c;
    }
    __syncthreads();
    float mu  = sh[0] * (1.f / CC);
    float var = sh[8] * (1.f / CC) - mu * mu;
    float rs  = rsqrtf(var + 1e-3f);
#pragma unroll
    for (int e = 0; e < 6; e++) {
        int c = tid + 256 * e;
        out[(size_t)row * CC + c] = __float2half_rn((v[e] - mu) * rs * g[c] + b[c]);
    }
}

// ---------------- fp16 mma NT GEMM ----------------
// MODE 0: fp32 out (+bias)(+resid)  MODE 1: fp16 out (+bias)(+relu)  MODE 3: fused QK
template<int MODE>
__global__ void __launch_bounds__(256, 2) mma_gemm(
    const __half* __restrict__ A, int lda, long long strA,
    const __half* __restrict__ B, int ldb, long long strB,
    void* __restrict__ Cv, int ldc, long long strC,
    int M, int N, int Kd,
    const float* __restrict__ bias,
    const float* __restrict__ resid,
    int do_relu)
{
    const int row0 = blockIdx.y * 128, col0 = blockIdx.x * 128;
    extern __shared__ char smem[];
    const int tid = threadIdx.x;
    const int wid = tid >> 5, lane = tid & 31;
    const int wr = wid >> 2, wc = wid & 3;
    const long long z = blockIdx.z;
    A += z * strA; B += z * strB;

    auto stage = [&](int kc, int buf) {
        const __half* Ak = A + (size_t)kc * 64;
        const __half* Bk = B + (size_t)kc * 64;
        char* sAb = smem + buf * 16384;
        char* sBb = smem + 32768 + buf * 16384;
#pragma unroll
        for (int it = 0; it < 4; it++) {
            int linear = tid + it * 256;
            int r = linear >> 3, g = linear & 7;
            int ra = row0 + r; if (ra >= M) ra = M - 1;
            uint32_t dst = smem_u32(sAb + r * 128 + ((g ^ (r & 7)) << 4));
            CP_ASYNC16(dst, Ak + (size_t)ra * lda + g * 8);
        }
#pragma unroll
        for (int it = 0; it < 4; it++) {
            int linear = tid + it * 256;
            int r = linear >> 3, g = linear & 7;
            int rb = col0 + r; if (rb >= N) rb = N - 1;
            uint32_t dst = smem_u32(sBb + r * 128 + ((g ^ (r & 7)) << 4));
            CP_ASYNC16(dst, Bk + (size_t)rb * ldb + g * 8);
        }
    };

    float acc[16][4] = {};
    const int nc = Kd >> 6;
    stage(0, 0);
    CP_COMMIT();
    for (int kc = 0; kc < nc; kc++) {
        int buf = kc & 1;
        if (kc + 1 < nc) { stage(kc + 1, buf ^ 1); CP_COMMIT(); CP_WAIT(1); }
        else             { CP_WAIT(0); }
        __syncthreads();
        const char* sAb = smem + buf * 16384;
        const char* sBb = smem + 32768 + buf * 16384;
#pragma unroll
        for (int ks = 0; ks < 4; ks++) {
            int gb = ks * 2 + (lane >> 4);
            uint32_t a[4][4], bfr[4][2];
#pragma unroll
            for (int mi = 0; mi < 4; mi++) {
                int r = wr * 64 + mi * 16 + (lane & 15);
                uint32_t ad = smem_u32(sAb + r * 128 + ((gb ^ (r & 7)) << 4));
                LDSM4(a[mi][0], a[mi][1], a[mi][2], a[mi][3], ad);
            }
#pragma unroll
            for (int nb = 0; nb < 2; nb++) {
                int n = wc * 32 + nb * 16 + (lane & 15);
                uint32_t ad = smem_u32(sBb + n * 128 + ((gb ^ (n & 7)) << 4));
                uint32_t q0, q1, q2, q3;
                LDSM4(q0, q1, q2, q3, ad);
                bfr[nb * 2][0] = q0;     bfr[nb * 2][1] = q2;
                bfr[nb * 2 + 1][0] = q1; bfr[nb * 2 + 1][1] = q3;
            }
#pragma unroll
            for (int mi = 0; mi < 4; mi++)
#pragma unroll
                for (int nj = 0; nj < 4; nj++)
                    mma16(acc[mi * 4 + nj], a[mi], bfr[nj]);
        }
        __syncthreads();
    }

#pragma unroll
    for (int mi = 0; mi < 4; mi++) {
#pragma unroll
        for (int hf = 0; hf < 2; hf++) {
            int r = row0 + wr * 64 + mi * 16 + (lane >> 2) + hf * 8;
            if (r >= M) continue;
#pragma unroll
            for (int nj = 0; nj < 4; nj++) {
                int cn = col0 + wc * 32 + nj * 8 + (lane & 3) * 2;
                float v0 = acc[mi * 4 + nj][hf * 2];
                float v1 = acc[mi * 4 + nj][hf * 2 + 1];
                if constexpr (MODE == 0) {
                    if (cn >= N) continue;
                    float* C = (float*)Cv + z * strC;
                    if (bias) { v0 += bias[cn]; v1 += bias[cn + 1]; }
                    if (resid) {
                        v0 += resid[(size_t)r * ldc + cn];
                        v1 += resid[(size_t)r * ldc + cn + 1];
                    }
                    *(float2*)(C + (size_t)r * ldc + cn) = make_float2(v0, v1);
                } else if constexpr (MODE == 1) {
                    if (cn >= N) continue;
                    __half* C = (__half*)Cv + z * strC;
                    if (bias) { v0 += bias[cn]; v1 += bias[cn + 1]; }
                    if (do_relu) { v0 = fmaxf(v0, 0.f); v1 = fmaxf(v1, 0.f); }
                    __half2 t;
                    t.x = __float2half_rn(v0); t.y = __float2half_rn(v1);
                    *(__half2*)(C + (size_t)r * ldc + cn) = t;
                } else {  // MODE 3: fused QK epilogue
                    if (cn < HK) {
                        __half2 tw, tr;
                        tw.x = __float2half_rn(v0 + bias[cn]);
                        tw.y = __float2half_rn(v1 + bias[cn + 1]);
                        tr.x = __float2half_rn(v0 + resid[cn]);
                        tr.y = __float2half_rn(v1 + resid[cn + 1]);
                        *(__half2*)(h_qw + (size_t)r * HK + cn) = tw;
                        *(__half2*)(h_qr + (size_t)r * HK + cn) = tr;
                    } else {
                        __half2 tk;
                        tk.x = __float2half_rn(v0); tk.y = __float2half_rn(v1);
                        *(__half2*)(h_k + (size_t)r * HK + cn - HK) = tk;
                    }
                }
            }
        }
    }
}

// ---------------- fused band logits: content + shifted rel, single write ----------------
// smem: sQw 0..16K, sQr 16K..32K, sK 32K..48K, sRk 48K..80K, sTile 80K..(80K+128*132*4)
#define LT_QW 0
#define LT_QR 16384
#define LT_K  32768
#define LT_RK 49152
#define LT_TILE 81920
#define LT_SMEM (81920 + 128 * 132 * 4)

__global__ void __launch_bounds__(256, 1) logits_kernel(float* __restrict__ logits) {
    extern __shared__ char smem[];
    float* sTile = (float*)(smem + LT_TILE);
    const int h = blockIdx.z;
    const int q0 = blockIdx.y * 128, j0 = blockIdx.x * 128;
    const int tid = threadIdx.x;
    const int wid = tid >> 5, lane = tid & 31;
    const int wr = wid >> 2, wc = wid & 3;
    const int hoff = h * 64;
    const int base = (Tq - 1) + j0 - q0;   // m at (jl=0, ql=0)

    // stage qw, qr, k (128 rows x 64h) and rk window (256 rows x 64h)
#pragma unroll
    for (int it = 0; it < 4; it++) {
        int linear = tid + it * 256;
        int r = linear >> 3, g = linear & 7;
        uint32_t sw = (uint32_t)(r * 128 + ((g ^ (r & 7)) << 4));
        CP_ASYNC16(smem_u32(smem + LT_QW + sw), h_qw + (size_t)(q0 + r) * HK + hoff + g * 8);
        CP_ASYNC16(smem_u32(smem + LT_QR + sw), h_qr + (size_t)(q0 + r) * HK + hoff + g * 8);
        CP_ASYNC16(smem_u32(smem + LT_K + sw), h_k + (size_t)(j0 + r) * HK + hoff + g * 8);
    }
#pragma unroll
    for (int it = 0; it < 8; it++) {
        int linear = tid + it * 256;
        int r = linear >> 3, g = linear & 7;
        int m = base - 128 + r;
        if (m < 0) m = 0;
        if (m > T2 - 1) m = T2 - 1;
        uint32_t sw = (uint32_t)(r * 128 + ((g ^ (r & 7)) << 4));
        CP_ASYNC16(smem_u32(smem + LT_RK + sw), h_rk + (size_t)m * HK + hoff + g * 8);
    }
    CP_COMMIT();
    // zero sTile while loads fly
    for (int i = tid; i < 128 * 132; i += 256) sTile[i] = 0.f;
    CP_WAIT(0);
    __syncthreads();

    // rel band: two 128x128x64 GEMMs (qr @ rk-window^T), scatter into sTile
#pragma unroll
    for (int half = 0; half < 2; half++) {
        float acc[16][4] = {};
#pragma unroll
        for (int ks = 0; ks < 4; ks++) {
            int gb = ks * 2 + (lane >> 4);
            uint32_t a[4][4], bfr[4][2];
#pragma unroll
            for (int mi = 0; mi < 4; mi++) {
                int r = wr * 64 + mi * 16 + (lane & 15);
                LDSM4(a[mi][0], a[mi][1], a[mi][2], a[mi][3],
                      smem_u32(smem + LT_QR + r * 128 + ((gb ^ (r & 7)) << 4)));
            }
#pragma unroll
            for (int nb = 0; nb < 2; nb++) {
                int n = half * 128 + wc * 32 + nb * 16 + (lane & 15);
                uint32_t p0, p1, p2, p3;
                LDSM4(p0, p1, p2, p3,
                      smem_u32(smem + LT_RK + n * 128 + ((gb ^ (n & 7)) << 4)));
                bfr[nb * 2][0] = p0;     bfr[nb * 2][1] = p2;
                bfr[nb * 2 + 1][0] = p1; bfr[nb * 2 + 1][1] = p3;
            }
#pragma unroll
            for (int mi = 0; mi < 4; mi++)
#pragma unroll
                for (int nj = 0; nj < 4; nj++)
                    mma16(acc[mi * 4 + nj], a[mi], bfr[nj]);
        }
        // scatter: jl = d - 128 + ql  (race-free: unique (ql, jl) per slot)
#pragma unroll
        for (int mi = 0; mi < 4; mi++)
#pragma unroll
            for (int hf = 0; hf < 2; hf++) {
                int ql = wr * 64 + mi * 16 + (lane >> 2) + hf * 8;
                float* trow = sTile + ql * 132;
#pragma unroll
                for (int nj = 0; nj < 4; nj++) {
                    int d = half * 128 + wc * 32 + nj * 8 + (lane & 3) * 2;
                    int jl = d - 128 + ql;
                    if (jl >= 0 && jl < 128) trow[jl] += acc[mi * 4 + nj][hf * 2];
                    if (jl + 1 >= 0 && jl + 1 < 128) trow[jl + 1] += acc[mi * 4 + nj][hf * 2 + 1];
                }
            }
    }

    // content GEMM (qw @ k^T)
    float acc[16][4] = {};
#pragma unroll
    for (int ks = 0; ks < 4; ks++) {
        int gb = ks * 2 + (lane >> 4);
        uint32_t a[4][4], bfr[4][2];
#pragma unroll
        for (int mi = 0; mi < 4; mi++) {
            int r = wr * 64 + mi * 16 + (lane & 15);
            LDSM4(a[mi][0], a[mi][1], a[mi][2], a[mi][3],
                  smem_u32(smem + LT_QW + r * 128 + ((gb ^ (r & 7)) << 4)));
        }
#pragma unroll
        for (int nb = 0; nb < 2; nb++) {
            int n = wc * 32 + nb * 16 + (lane & 15);
            uint32_t p0, p1, p2, p3;
            LDSM4(p0, p1, p2, p3,
                  smem_u32(smem + LT_K + n * 128 + ((gb ^ (n & 7)) << 4)));
            bfr[nb * 2][0] = p0;     bfr[nb * 2][1] = p2;
            bfr[nb * 2 + 1][0] = p1; bfr[nb * 2 + 1][1] = p3;
        }
#pragma unroll
        for (int mi = 0; mi < 4; mi++)
#pragma unroll
            for (int nj = 0; nj < 4; nj++)
                mma16(acc[mi * 4 + nj], a[mi], bfr[nj]);
    }
    __syncthreads();   // all scatters visible before epilogue reads sTile

    // epilogue: logits = content + band(rel), single write
#pragma unroll
    for (int mi = 0; mi < 4; mi++)
#pragma unroll
        for (int hf = 0; hf < 2; hf++) {
            int ql = wr * 64 + mi * 16 + (lane >> 2) + hf * 8;
            float* lrow = logits + ((size_t)h * Tq + q0 + ql) * Tq + j0;
            const float* trow = sTile + ql * 132;
#pragma unroll
            for (int nj = 0; nj < 4; nj++) {
                int cn = wc * 32 + nj * 8 + (lane & 3) * 2;
                float v0 = acc[mi * 4 + nj][hf * 2] + trow[cn];
                float v1 = acc[mi * 4 + nj][hf * 2 + 1] + trow[cn + 1];
                *(float2*)(lrow + cn) = make_float2(v0, v1);
            }
        }
}

// ---------------- positional features -> fp16 ----------------
__global__ void posfeat_kernel(__half* __restrict__ pos) {
    int warp = threadIdx.x >> 5, lane = threadIdx.x & 31;
    int p = blockIdx.x * 8 + warp;
    if (p >= T2) return;
    float d = (float)(p - (Tq - 1));
    float ap = fabsf(d);
    float sgn = (d > 0.f) ? 1.f : ((d < 0.f) ? -1.f : 0.f);
    double hi = 10.584962500721156;    // log2(1536)
    double exx = 3.0 + (hi - 3.0) * (double)lane / 31.0;
    float half_life = (float)exp2(exx);
    float coef = (float)(-(0.6931471805599453 / (double)half_life));
    float fexp = expf(ap * coef);
    float width = exp2f((float)(lane + 1)) - 1.f;
    float fcm = (width > ap) ? 1.f : 0.f;
    double mean = 48.0 + (1536.0 - 48.0) * (double)lane / 31.0;
    float conc = (float)((mean / 24.0) * (mean / 24.0));
    float rate = (float)(mean / 576.0);
    float log_unnorm = (conc - 1.f) * logf(ap) - rate * ap;
    float log_norm = lgammaf(conc) - conc * logf(rate);
    float prob = expf(log_unnorm - log_norm) + 1e-8f;
    float mx = prob;
#pragma unroll
    for (int o = 16; o > 0; o >>= 1) mx = fmaxf(mx, __shfl_xor_sync(0xffffffffu, mx, o));
    float fg = prob / mx;
    __half* row = pos + (size_t)p * FF;
    row[lane]       = __float2half_rn(fexp);
    row[32 + lane]  = __float2half_rn(fcm);
    row[64 + lane]  = __float2half_rn(fg);
    row[96 + lane]  = __float2half_rn(sgn * fexp);
    row[128 + lane] = __float2half_rn(sgn * fcm);
    row[160 + lane] = __float2half_rn(sgn * fg);
}

// ---------------- softmax: fp32 logits -> fp16 probs ----------------
__global__ void softmax_kernel(const float* __restrict__ logits, __half* __restrict__ probs) {
    int q = blockIdx.x, h = blockIdx.y;
    int tid = threadIdx.x;
    const float* row = logits + ((size_t)h * Tq + q) * Tq;
    __half* prow = probs + ((size_t)h * Tq + q) * Tq;
    float v[6];
    float mx = -1e30f;
#pragma unroll
    for (int e = 0; e < 6; e++) {
        v[e] = row[tid + 256 * e];
        mx = fmaxf(mx, v[e]);
    }
    __shared__ float sh[8];
#pragma unroll
    for (int o = 16; o > 0; o >>= 1) mx = fmaxf(mx, __shfl_xor_sync(0xffffffffu, mx, o));
    int wid = tid >> 5, lane = tid & 31;
    if (lane == 0) sh[wid] = mx;
    __syncthreads();
    if (tid == 0) { float m = sh[0]; for (int i = 1; i < 8; i++) m = fmaxf(m, sh[i]); sh[0] = m; }
    __syncthreads();
    mx = sh[0];
    __syncthreads();
    float s = 0.f;
#pragma unroll
    for (int e = 0; e < 6; e++) { v[e] = expf(v[e] - mx); s += v[e]; }
#pragma unroll
    for (int o = 16; o > 0; o >>= 1) s += __shfl_xor_sync(0xffffffffu, s, o);
    if (lane == 0) sh[wid] = s;
    __syncthreads();
    if (tid == 0) { float m = 0.f; for (int i = 0; i < 8; i++) m += sh[i]; sh[0] = m; }
    __syncthreads();
    float inv = 1.f / sh[0];
#pragma unroll
    for (int e = 0; e < 6; e++) prow[tid + 256 * e] = __float2half_rn(v[e] * inv);
}

// ---------------- host ----------------
#define GSMEM 65536

extern "C" void kernel_launch(void* const* d_in, const int* in_sizes, int n_in,
                              void* d_out, int out_size) {
    (void)in_sizes; (void)n_in; (void)out_size;
    const float* x     = (const float*)d_in[0];
    const float* ln1_g = (const float*)d_in[1];
    const float* ln1_b = (const float*)d_in[2];
    const float* ln2_g = (const float*)d_in[3];
    const float* ln2_b = (const float*)d_in[4];
    const float* Wq    = (const float*)d_in[5];
    const float* Wk    = (const float*)d_in[6];
    const float* Wv    = (const float*)d_in[7];
    const float* Wr    = (const float*)d_in[8];
    const float* Wo    = (const float*)d_in[9];
    const float* bo    = (const float*)d_in[10];
    const float* rwb   = (const float*)d_in[11];
    const float* rrb   = (const float*)d_in[12];
    const float* W1    = (const float*)d_in[13];
    const float* b1    = (const float*)d_in[14];
    const float* W2    = (const float*)d_in[15];
    const float* b2    = (const float*)d_in[16];
    float* out = (float*)d_out;

    cudaFuncSetAttribute(mma_gemm<0>, cudaFuncAttributeMaxDynamicSharedMemorySize, GSMEM);
    cudaFuncSetAttribute(mma_gemm<1>, cudaFuncAttributeMaxDynamicSharedMemorySize, GSMEM);
    cudaFuncSetAttribute(mma_gemm<3>, cudaFuncAttributeMaxDynamicSharedMemorySize, GSMEM);
    cudaFuncSetAttribute(logits_kernel, cudaFuncAttributeMaxDynamicSharedMemorySize, LT_SMEM);

    float *logits, *y;
    __half *xn, *vT, *pos, *rk, *probs, *o, *yn, *h1;
    __half *WqkT, *WvT, *WrT, *WoT, *W1T, *W2T;
    cudaGetSymbolAddress((void**)&logits, g_logits);
    cudaGetSymbolAddress((void**)&y, g_y);
    cudaGetSymbolAddress((void**)&xn, h_xn);
    cudaGetSymbolAddress((void**)&vT, h_vT);
    cudaGetSymbolAddress((void**)&pos, h_pos);
    cudaGetSymbolAddress((void**)&rk, h_rk);
    cudaGetSymbolAddress((void**)&probs, h_probs);
    cudaGetSymbolAddress((void**)&o, h_o);
    cudaGetSymbolAddress((void**)&yn, h_yn);
    cudaGetSymbolAddress((void**)&h1, h_h1);
    cudaGetSymbolAddress((void**)&WqkT, h_WqkT);
    cudaGetSymbolAddress((void**)&WvT, h_WvT);
    cudaGetSymbolAddress((void**)&WrT, h_WrT);
    cudaGetSymbolAddress((void**)&WoT, h_WoT);
    cudaGetSymbolAddress((void**)&W1T, h_W1T);
    cudaGetSymbolAddress((void**)&W2T, h_W2T);

    // all weight transposes in one launch
    transpose_all<<<15456, dim3(32, 8)>>>(Wq, Wk, Wv, Wr, Wo, W1, W2);
    // LN1
    ln_kernel<<<Tq, 256>>>(x, ln1_g, ln1_b, xn);
    // fused QK: writes qw, qr, k (scale folded into WqT)
    mma_gemm<3><<<dim3(8, 12), 256, GSMEM>>>(
        xn, CC, 0, WqkT, CC, 0, nullptr, 0, 0, Tq, HK * 2, CC, rwb, rrb, 0);
    // vT = WvT @ xn^T
    mma_gemm<1><<<dim3(12, 12), 256, GSMEM>>>(
        WvT, CC, 0, xn, CC, 0, vT, Tq, 0, HV, Tq, CC, nullptr, nullptr, 0);
    // positional features + rk
    posfeat_kernel<<<(T2 + 7) / 8, 256>>>(pos);
    mma_gemm<1><<<dim3(4, 24), 256, GSMEM>>>(
        pos, FF, 0, WrT, FF, 0, rk, HK, 0, T2, HK, FF, nullptr, nullptr, 0);
    // fused band logits (content + shifted rel), single write
    logits_kernel<<<dim3(12, 12, NH), 256, LT_SMEM>>>(logits);
    // softmax -> half probs
    softmax_kernel<<<dim3(Tq, NH), 256>>>(logits, probs);
    // o = probs @ v
    mma_gemm<1><<<dim3(2, 12, NH), 256, GSMEM>>>(
        probs, Tq, (long long)Tq * Tq, vT, Tq, (long long)VH * Tq,
        o, HV, VH, Tq, VH, Tq, nullptr, nullptr, 0);
    // y = x + o @ Wo + bo
    mma_gemm<0><<<dim3(12, 12), 256, GSMEM>>>(
        o, HV, 0, WoT, HV, 0, y, CC, 0, Tq, CC, HV, bo, x, 0);
    // LN2 + MLP
    ln_kernel<<<Tq, 256>>>(y, ln2_g, ln2_b, yn);
    mma_gemm<1><<<dim3(24, 12), 256, GSMEM>>>(
        yn, CC, 0, W1T, CC, 0, h1, D1, 0, Tq, D1, CC, b1, nullptr, 1);
    mma_gemm<0><<<dim3(12, 12), 256, GSMEM>>>(
        h1, D1, 0, W2T, D1, 0, out, CC, 0, Tq, CC, D1, b2, y, 0);
}

// round 7
// speedup vs baseline: 5.9282x; 1.0110x over previous
#include <cuda_runtime.h>
#include <cuda_fp16.h>
#include <cstdint>
#include <math.h>

#define Tq 1536
#define CC 1536
#define T2 3071
#define NH 8
#define KH 64
#define VH 192
#define FF 192
#define HK 512
#define HV 1536
#define D1 3072

// ---------------- PTX helpers ----------------
__device__ __forceinline__ uint32_t smem_u32(const void* p) {
    uint32_t a;
    asm("{ .reg .u64 t; cvta.to.shared.u64 t, %1; cvt.u32.u64 %0, t; }" : "=r"(a) : "l"(p));
    return a;
}
#define CP_ASYNC16(dst, src) \
    asm volatile("cp.async.ca.shared.global [%0], [%1], 16;" :: "r"(dst), "l"(src) : "memory")
#define CP_COMMIT() asm volatile("cp.async.commit_group;" ::: "memory")
#define CP_WAIT(n)  asm volatile("cp.async.wait_group %0;" :: "n"(n) : "memory")
#define LDSM4(r0, r1, r2, r3, addr) \
    asm volatile("ldmatrix.sync.aligned.m8n8.x4.shared.b16 {%0,%1,%2,%3}, [%4];" \
        : "=r"(r0), "=r"(r1), "=r"(r2), "=r"(r3) : "r"(addr))

__device__ __forceinline__ void mma16(float* c, const uint32_t* a, const uint32_t* b) {
    asm volatile(
        "mma.sync.aligned.m16n8k16.row.col.f32.f16.f16.f32 "
        "{%0,%1,%2,%3}, {%4,%5,%6,%7}, {%8,%9}, {%0,%1,%2,%3};"
        : "+f"(c[0]), "+f"(c[1]), "+f"(c[2]), "+f"(c[3])
        : "r"(a[0]), "r"(a[1]), "r"(a[2]), "r"(a[3]), "r"(b[0]), "r"(b[1]));
}

// ---------------- scratch ----------------
__device__ __align__(128) float  g_logits[(size_t)NH * Tq * Tq];
__device__ __align__(128) float  g_y[Tq * CC];
__device__ __align__(128) __half h_xn[Tq * CC];
__device__ __align__(128) __half h_qw[Tq * HK];
__device__ __align__(128) __half h_qr[Tq * HK];
__device__ __align__(128) __half h_k[Tq * HK];
__device__ __align__(128) __half h_vT[HV * Tq];
__device__ __align__(128) __half h_pos[(T2 + 1) * FF];
__device__ __align__(128) __half h_rk[(T2 + 1) * HK];
__device__ __align__(128) __half h_probs[(size_t)NH * Tq * Tq];
__device__ __align__(128) __half h_o[Tq * HV];
__device__ __align__(128) __half h_yn[Tq * CC];
__device__ __align__(128) __half h_h1[Tq * D1];
__device__ __align__(128) __half h_WqkT[(HK * 2) * CC];
__device__ __align__(128) __half h_WvT[HV * CC];
__device__ __align__(128) __half h_WrT[HK * FF];
__device__ __align__(128) __half h_WoT[CC * HV];
__device__ __align__(128) __half h_W1T[D1 * CC];
__device__ __align__(128) __half h_W2T[CC * D1];

// ---------------- merged transpose: all 7 weights in one launch ----------------
__global__ void transpose_all(const float* __restrict__ Wq, const float* __restrict__ Wk,
                              const float* __restrict__ Wv, const float* __restrict__ Wr,
                              const float* __restrict__ Wo, const float* __restrict__ W1,
                              const float* __restrict__ W2) {
    int b = blockIdx.x;
    const float* in; __half* out; int Rr, Cc, bx, by; float scale = 1.f;
    if (b < 768)        { in = Wq; out = h_WqkT; Rr = CC; Cc = HK; scale = 0.125f; bx = b % 16; by = b / 16; }
    else if (b < 1536)  { b -= 768;  in = Wk; out = h_WqkT + (size_t)HK * CC; Rr = CC; Cc = HK; bx = b % 16; by = b / 16; }
    else if (b < 3840)  { b -= 1536; in = Wv; out = h_WvT; Rr = CC; Cc = HV; bx = b % 48; by = b / 48; }
    else if (b < 3936)  { b -= 3840; in = Wr; out = h_WrT; Rr = FF; Cc = HK; bx = b % 16; by = b / 16; }
    else if (b < 6240)  { b -= 3936; in = Wo; out = h_WoT; Rr = HV; Cc = CC; bx = b % 48; by = b / 48; }
    else if (b < 10848) { b -= 6240; in = W1; out = h_W1T; Rr = CC; Cc = D1; bx = b % 96; by = b / 96; }
    else                { b -= 10848; in = W2; out = h_W2T; Rr = D1; Cc = CC; bx = b % 48; by = b / 48; }
    __shared__ float t[32][33];
    int c0 = bx * 32, r0 = by * 32;
    int tx = threadIdx.x, ty = threadIdx.y;   // 32 x 8
#pragma unroll
    for (int i = 0; i < 4; i++)
        t[ty + 8 * i][tx] = in[(size_t)(r0 + ty + 8 * i) * Cc + c0 + tx];
    __syncthreads();
#pragma unroll
    for (int i = 0; i < 4; i++)
        out[(size_t)(c0 + ty + 8 * i) * Rr + r0 + tx] = __float2half_rn(t[tx][ty + 8 * i] * scale);
}

// ---------------- layernorm fp32 -> fp16 ----------------
__global__ void ln_kernel(const float* __restrict__ x, const float* __restrict__ g,
                          const float* __restrict__ b, __half* __restrict__ out) {
    int row = blockIdx.x;
    int tid = threadIdx.x;
    const float* xr = x + (size_t)row * CC;
    float v[6];
    float s = 0.f, s2 = 0.f;
#pragma unroll
    for (int e = 0; e < 6; e++) {
        float t = xr[tid + 256 * e];
        v[e] = t; s += t; s2 += t * t;
    }
    __shared__ float sh[16];
#pragma unroll
    for (int o = 16; o > 0; o >>= 1) {
        s  += __shfl_xor_sync(0xffffffffu, s, o);
        s2 += __shfl_xor_sync(0xffffffffu, s2, o);
    }
    int wid = tid >> 5, lane = tid & 31;
    if (lane == 0) { sh[wid] = s; sh[8 + wid] = s2; }
    __syncthreads();
    if (tid == 0) {
        float a = 0.f, c = 0.f;
        for (int i = 0; i < 8; i++) { a += sh[i]; c += sh[8 + i]; }
        sh[0] = a; sh[8] = c;
    }
    __syncthreads();
    float mu  = sh[0] * (1.f / CC);
    float var = sh[8] * (1.f / CC) - mu * mu;
    float rs  = rsqrtf(var + 1e-3f);
#pragma unroll
    for (int e = 0; e < 6; e++) {
        int c = tid + 256 * e;
        out[(size_t)row * CC + c] = __float2half_rn((v[e] - mu) * rs * g[c] + b[c]);
    }
}

// ---------------- fp16 mma NT GEMM (3-stage pipeline, XOR-swizzle addrs) ----------------
// MODE 0: fp32 out (+bias)(+resid)  MODE 1: fp16 out (+bias)(+relu)  MODE 3: fused QK
template<int MODE>
__global__ void __launch_bounds__(256) mma_gemm(
    const __half* __restrict__ A, int lda, long long strA,
    const __half* __restrict__ B, int ldb, long long strB,
    void* __restrict__ Cv, int ldc, long long strC,
    int M, int N, int Kd,
    const float* __restrict__ bias,
    const float* __restrict__ resid,
    int do_relu)
{
    const int row0 = blockIdx.y * 128, col0 = blockIdx.x * 128;
    extern __shared__ char smem_raw[];
    const uint32_t sbase = (smem_u32(smem_raw) + 127) & ~127u;
    const int tid = threadIdx.x;
    const int wid = tid >> 5, lane = tid & 31;
    const int wr = wid >> 2, wc = wid & 3;
    const long long z = blockIdx.z;
    A += z * strA; B += z * strB;

    // staging addresses (precomputed; per-stage base added later)
    uint32_t stOff[4];
    const __half* gA[4];
    const __half* gB[4];
#pragma unroll
    for (int it = 0; it < 4; it++) {
        int linear = tid + it * 256;
        int r = linear >> 3, g = linear & 7;
        stOff[it] = (uint32_t)(r * 128 + ((g ^ (r & 7)) << 4));
        int ra = row0 + r; if (ra >= M) ra = M - 1;
        int rb = col0 + r; if (rb >= N) rb = N - 1;
        gA[it] = A + (size_t)ra * lda + g * 8;
        gB[it] = B + (size_t)rb * ldb + g * 8;
    }
    auto stage = [&](int kc, int s) {
        uint32_t aS = sbase + s * 16384;
        uint32_t bS = sbase + 49152 + s * 16384;
        size_t koff = (size_t)kc * 64;
#pragma unroll
        for (int it = 0; it < 4; it++) {
            CP_ASYNC16(aS + stOff[it], gA[it] + koff);
            CP_ASYNC16(bS + stOff[it], gB[it] + koff);
        }
    };

    // fragment base offsets (XOR trick: addr = (base+off) ^ (gb<<4), bases 128-aligned)
    uint32_t offA[4], offB[2];
#pragma unroll
    for (int mi = 0; mi < 4; mi++) {
        int r = wr * 64 + mi * 16 + (lane & 15);
        offA[mi] = (uint32_t)(r * 128 + ((r & 7) << 4));
    }
#pragma unroll
    for (int nb = 0; nb < 2; nb++) {
        int n = wc * 32 + nb * 16 + (lane & 15);
        offB[nb] = (uint32_t)(n * 128 + ((n & 7) << 4));
    }
    const uint32_t laneSel = (uint32_t)(lane >> 4) << 4;

    float acc[16][4] = {};
    const int nc = Kd >> 6;
    stage(0, 0); CP_COMMIT();
    if (nc > 1) stage(1, 1);
    CP_COMMIT();
    for (int kc = 0; kc < nc; kc++) {
        int s = kc % 3;
        CP_WAIT(1);
        __syncthreads();
        if (kc + 2 < nc) stage(kc + 2, (kc + 2) % 3);
        CP_COMMIT();
        uint32_t aS = sbase + s * 16384;
        uint32_t bS = sbase + 49152 + s * 16384;
#pragma unroll
        for (int ks = 0; ks < 4; ks++) {
            uint32_t gsel = ((uint32_t)(ks * 2) << 4) ^ laneSel;
            uint32_t a[4][4], bfr[4][2];
#pragma unroll
            for (int mi = 0; mi < 4; mi++)
                LDSM4(a[mi][0], a[mi][1], a[mi][2], a[mi][3], (aS + offA[mi]) ^ gsel);
#pragma unroll
            for (int nb = 0; nb < 2; nb++) {
                uint32_t q0, q1, q2, q3;
                LDSM4(q0, q1, q2, q3, (bS + offB[nb]) ^ gsel);
                bfr[nb * 2][0] = q0;     bfr[nb * 2][1] = q2;
                bfr[nb * 2 + 1][0] = q1; bfr[nb * 2 + 1][1] = q3;
            }
#pragma unroll
            for (int mi = 0; mi < 4; mi++)
#pragma unroll
                for (int nj = 0; nj < 4; nj++)
                    mma16(acc[mi * 4 + nj], a[mi], bfr[nj]);
        }
        __syncthreads();
    }

#pragma unroll
    for (int mi = 0; mi < 4; mi++) {
#pragma unroll
        for (int hf = 0; hf < 2; hf++) {
            int r = row0 + wr * 64 + mi * 16 + (lane >> 2) + hf * 8;
            if (r >= M) continue;
#pragma unroll
            for (int nj = 0; nj < 4; nj++) {
                int cn = col0 + wc * 32 + nj * 8 + (lane & 3) * 2;
                float v0 = acc[mi * 4 + nj][hf * 2];
                float v1 = acc[mi * 4 + nj][hf * 2 + 1];
                if constexpr (MODE == 0) {
                    if (cn >= N) continue;
                    float* C = (float*)Cv + z * strC;
                    if (bias) { v0 += bias[cn]; v1 += bias[cn + 1]; }
                    if (resid) {
                        v0 += resid[(size_t)r * ldc + cn];
                        v1 += resid[(size_t)r * ldc + cn + 1];
                    }
                    *(float2*)(C + (size_t)r * ldc + cn) = make_float2(v0, v1);
                } else if constexpr (MODE == 1) {
                    if (cn >= N) continue;
                    __half* C = (__half*)Cv + z * strC;
                    if (bias) { v0 += bias[cn]; v1 += bias[cn + 1]; }
                    if (do_relu) { v0 = fmaxf(v0, 0.f); v1 = fmaxf(v1, 0.f); }
                    __half2 t;
                    t.x = __float2half_rn(v0); t.y = __float2half_rn(v1);
                    *(__half2*)(C + (size_t)r * ldc + cn) = t;
                } else {  // MODE 3: fused QK epilogue
                    if (cn < HK) {
                        __half2 tw, tr;
                        tw.x = __float2half_rn(v0 + bias[cn]);
                        tw.y = __float2half_rn(v1 + bias[cn + 1]);
                        tr.x = __float2half_rn(v0 + resid[cn]);
                        tr.y = __float2half_rn(v1 + resid[cn + 1]);
                        *(__half2*)(h_qw + (size_t)r * HK + cn) = tw;
                        *(__half2*)(h_qr + (size_t)r * HK + cn) = tr;
                    } else {
                        __half2 tk;
                        tk.x = __float2half_rn(v0); tk.y = __float2half_rn(v1);
                        *(__half2*)(h_k + (size_t)r * HK + cn - HK) = tk;
                    }
                }
            }
        }
    }
}

// ---------------- fused band logits: content + shifted rel, single write ----------------
#define LT_QW 0
#define LT_QR 16384
#define LT_K  32768
#define LT_RK 49152
#define LT_TILE 81920
#define LT_SMEM (81920 + 128 * 132 * 4 + 128)

__global__ void __launch_bounds__(256, 1) logits_kernel(float* __restrict__ logits) {
    extern __shared__ char smem_raw[];
    const uint32_t sbase = (smem_u32(smem_raw) + 127) & ~127u;
    float* sTile = (float*)(smem_raw + ((sbase - smem_u32(smem_raw)) + LT_TILE));
    const int h = blockIdx.z;
    const int q0 = blockIdx.y * 128, j0 = blockIdx.x * 128;
    const int tid = threadIdx.x;
    const int wid = tid >> 5, lane = tid & 31;
    const int wr = wid >> 2, wc = wid & 3;
    const int hoff = h * 64;
    const int base = (Tq - 1) + j0 - q0;   // m at (jl=0, ql=0)

    // stage qw, qr, k (128x64h) and rk window (256x64h)
#pragma unroll
    for (int it = 0; it < 4; it++) {
        int linear = tid + it * 256;
        int r = linear >> 3, g = linear & 7;
        uint32_t sw = (uint32_t)(r * 128 + ((g ^ (r & 7)) << 4));
        CP_ASYNC16(sbase + LT_QW + sw, h_qw + (size_t)(q0 + r) * HK + hoff + g * 8);
        CP_ASYNC16(sbase + LT_QR + sw, h_qr + (size_t)(q0 + r) * HK + hoff + g * 8);
        CP_ASYNC16(sbase + LT_K + sw, h_k + (size_t)(j0 + r) * HK + hoff + g * 8);
    }
#pragma unroll
    for (int it = 0; it < 8; it++) {
        int linear = tid + it * 256;
        int r = linear >> 3, g = linear & 7;
        int m = base - 128 + r;
        if (m < 0) m = 0;
        if (m > T2 - 1) m = T2 - 1;
        uint32_t sw = (uint32_t)(r * 128 + ((g ^ (r & 7)) << 4));
        CP_ASYNC16(sbase + LT_RK + sw, h_rk + (size_t)m * HK + hoff + g * 8);
    }
    CP_COMMIT();
    for (int i = tid; i < 128 * 132; i += 256) sTile[i] = 0.f;
    CP_WAIT(0);
    __syncthreads();

    // precomputed fragment offsets
    uint32_t offRow[4], offN[2], offRk2[4];
#pragma unroll
    for (int mi = 0; mi < 4; mi++) {
        int r = wr * 64 + mi * 16 + (lane & 15);
        offRow[mi] = (uint32_t)(r * 128 + ((r & 7) << 4));
    }
#pragma unroll
    for (int nb = 0; nb < 2; nb++) {
        int n = wc * 32 + nb * 16 + (lane & 15);
        offN[nb] = (uint32_t)(n * 128 + ((n & 7) << 4));
#pragma unroll
        for (int half = 0; half < 2; half++) {
            int nn = half * 128 + n;
            offRk2[half * 2 + nb] = (uint32_t)(nn * 128 + ((nn & 7) << 4));
        }
    }
    const uint32_t laneSel = (uint32_t)(lane >> 4) << 4;

    // rel band: two 128x128x64 GEMMs (qr @ rk-window^T), scatter into sTile
#pragma unroll
    for (int half = 0; half < 2; half++) {
        float acc[16][4] = {};
#pragma unroll
        for (int ks = 0; ks < 4; ks++) {
            uint32_t gsel = ((uint32_t)(ks * 2) << 4) ^ laneSel;
            uint32_t a[4][4], bfr[4][2];
#pragma unroll
            for (int mi = 0; mi < 4; mi++)
                LDSM4(a[mi][0], a[mi][1], a[mi][2], a[mi][3],
                      (sbase + LT_QR + offRow[mi]) ^ gsel);
#pragma unroll
            for (int nb = 0; nb < 2; nb++) {
                uint32_t p0, p1, p2, p3;
                LDSM4(p0, p1, p2, p3, (sbase + LT_RK + offRk2[half * 2 + nb]) ^ gsel);
                bfr[nb * 2][0] = p0;     bfr[nb * 2][1] = p2;
                bfr[nb * 2 + 1][0] = p1; bfr[nb * 2 + 1][1] = p3;
            }
#pragma unroll
            for (int mi = 0; mi < 4; mi++)
#pragma unroll
                for (int nj = 0; nj < 4; nj++)
                    mma16(acc[mi * 4 + nj], a[mi], bfr[nj]);
        }
        // scatter: jl = d - 128 + ql (race-free per row)
#pragma unroll
        for (int mi = 0; mi < 4; mi++)
#pragma unroll
            for (int hf = 0; hf < 2; hf++) {
                int ql = wr * 64 + mi * 16 + (lane >> 2) + hf * 8;
                float* trow = sTile + ql * 132;
#pragma unroll
                for (int nj = 0; nj < 4; nj++) {
                    int d = half * 128 + wc * 32 + nj * 8 + (lane & 3) * 2;
                    int jl = d - 128 + ql;
                    if (jl >= 0 && jl < 128) trow[jl] += acc[mi * 4 + nj][hf * 2];
                    if (jl + 1 >= 0 && jl + 1 < 128) trow[jl + 1] += acc[mi * 4 + nj][hf * 2 + 1];
                }
            }
    }

    // content GEMM (qw @ k^T)
    float acc[16][4] = {};
#pragma unroll
    for (int ks = 0; ks < 4; ks++) {
        uint32_t gsel = ((uint32_t)(ks * 2) << 4) ^ laneSel;
        uint32_t a[4][4], bfr[4][2];
#pragma unroll
        for (int mi = 0; mi < 4; mi++)
            LDSM4(a[mi][0], a[mi][1], a[mi][2], a[mi][3],
                  (sbase + LT_QW + offRow[mi]) ^ gsel);
#pragma unroll
        for (int nb = 0; nb < 2; nb++) {
            uint32_t p0, p1, p2, p3;
            LDSM4(p0, p1, p2, p3, (sbase + LT_K + offN[nb]) ^ gsel);
            bfr[nb * 2][0] = p0;     bfr[nb * 2][1] = p2;
            bfr[nb * 2 + 1][0] = p1; bfr[nb * 2 + 1][1] = p3;
        }
#pragma unroll
        for (int mi = 0; mi < 4; mi++)
#pragma unroll
            for (int nj = 0; nj < 4; nj++)
                mma16(acc[mi * 4 + nj], a[mi], bfr[nj]);
    }
    __syncthreads();   // scatters visible before epilogue reads sTile

    // epilogue: logits = content + band(rel), single write
#pragma unroll
    for (int mi = 0; mi < 4; mi++)
#pragma unroll
        for (int hf = 0; hf < 2; hf++) {
            int ql = wr * 64 + mi * 16 + (lane >> 2) + hf * 8;
            float* lrow = logits + ((size_t)h * Tq + q0 + ql) * Tq + j0;
            const float* trow = sTile + ql * 132;
#pragma unroll
            for (int nj = 0; nj < 4; nj++) {
                int cn = wc * 32 + nj * 8 + (lane & 3) * 2;
                float v0 = acc[mi * 4 + nj][hf * 2] + trow[cn];
                float v1 = acc[mi * 4 + nj][hf * 2 + 1] + trow[cn + 1];
                *(float2*)(lrow + cn) = make_float2(v0, v1);
            }
        }
}

// ---------------- positional features -> fp16 ----------------
__global__ void posfeat_kernel(__half* __restrict__ pos) {
    int warp = threadIdx.x >> 5, lane = threadIdx.x & 31;
    int p = blockIdx.x * 8 + warp;
    if (p >= T2) return;
    float d = (float)(p - (Tq - 1));
    float ap = fabsf(d);
    float sgn = (d > 0.f) ? 1.f : ((d < 0.f) ? -1.f : 0.f);
    double hi = 10.584962500721156;    // log2(1536)
    double exx = 3.0 + (hi - 3.0) * (double)lane / 31.0;
    float half_life = (float)exp2(exx);
    float coef = (float)(-(0.6931471805599453 / (double)half_life));
    float fexp = expf(ap * coef);
    float width = exp2f((float)(lane + 1)) - 1.f;
    float fcm = (width > ap) ? 1.f : 0.f;
    double mean = 48.0 + (1536.0 - 48.0) * (double)lane / 31.0;
    float conc = (float)((mean / 24.0) * (mean / 24.0));
    float rate = (float)(mean / 576.0);
    float log_unnorm = (conc - 1.f) * logf(ap) - rate * ap;
    float log_norm = lgammaf(conc) - conc * logf(rate);
    float prob = expf(log_unnorm - log_norm) + 1e-8f;
    float mx = prob;
#pragma unroll
    for (int o = 16; o > 0; o >>= 1) mx = fmaxf(mx, __shfl_xor_sync(0xffffffffu, mx, o));
    float fg = prob / mx;
    __half* row = pos + (size_t)p * FF;
    row[lane]       = __float2half_rn(fexp);
    row[32 + lane]  = __float2half_rn(fcm);
    row[64 + lane]  = __float2half_rn(fg);
    row[96 + lane]  = __float2half_rn(sgn * fexp);
    row[128 + lane] = __float2half_rn(sgn * fcm);
    row[160 + lane] = __float2half_rn(sgn * fg);
}

// ---------------- softmax: fp32 logits -> fp16 probs ----------------
__global__ void softmax_kernel(const float* __restrict__ logits, __half* __restrict__ probs) {
    int q = blockIdx.x, h = blockIdx.y;
    int tid = threadIdx.x;
    const float* row = logits + ((size_t)h * Tq + q) * Tq;
    __half* prow = probs + ((size_t)h * Tq + q) * Tq;
    float v[6];
    float mx = -1e30f;
#pragma unroll
    for (int e = 0; e < 6; e++) {
        v[e] = row[tid + 256 * e];
        mx = fmaxf(mx, v[e]);
    }
    __shared__ float sh[8];
#pragma unroll
    for (int o = 16; o > 0; o >>= 1) mx = fmaxf(mx, __shfl_xor_sync(0xffffffffu, mx, o));
    int wid = tid >> 5, lane = tid & 31;
    if (lane == 0) sh[wid] = mx;
    __syncthreads();
    if (tid == 0) { float m = sh[0]; for (int i = 1; i < 8; i++) m = fmaxf(m, sh[i]); sh[0] = m; }
    __syncthreads();
    mx = sh[0];
    __syncthreads();
    float s = 0.f;
#pragma unroll
    for (int e = 0; e < 6; e++) { v[e] = expf(v[e] - mx); s += v[e]; }
#pragma unroll
    for (int o = 16; o > 0; o >>= 1) s += __shfl_xor_sync(0xffffffffu, s, o);
    if (lane == 0) sh[wid] = s;
    __syncthreads();
    if (tid == 0) { float m = 0.f; for (int i = 0; i < 8; i++) m += sh[i]; sh[0] = m; }
    __syncthreads();
    float inv = 1.f / sh[0];
#pragma unroll
    for (int e = 0; e < 6; e++) prow[tid + 256 * e] = __float2half_rn(v[e] * inv);
}

// ---------------- host ----------------
#define GSMEM (98304 + 128)

extern "C" void kernel_launch(void* const* d_in, const int* in_sizes, int n_in,
                              void* d_out, int out_size) {
    (void)in_sizes; (void)n_in; (void)out_size;
    const float* x     = (const float*)d_in[0];
    const float* ln1_g = (const float*)d_in[1];
    const float* ln1_b = (const float*)d_in[2];
    const float* ln2_g = (const float*)d_in[3];
    const float* ln2_b = (const float*)d_in[4];
    const float* Wq    = (const float*)d_in[5];
    const float* Wk    = (const float*)d_in[6];
    const float* Wv    = (const float*)d_in[7];
    const float* Wr    = (const float*)d_in[8];
    const float* Wo    = (const float*)d_in[9];
    const float* bo    = (const float*)d_in[10];
    const float* rwb   = (const float*)d_in[11];
    const float* rrb   = (const float*)d_in[12];
    const float* W1    = (const float*)d_in[13];
    const float* b1    = (const float*)d_in[14];
    const float* W2    = (const float*)d_in[15];
    const float* b2    = (const float*)d_in[16];
    float* out = (float*)d_out;

    cudaFuncSetAttribute(mma_gemm<0>, cudaFuncAttributeMaxDynamicSharedMemorySize, GSMEM);
    cudaFuncSetAttribute(mma_gemm<1>, cudaFuncAttributeMaxDynamicSharedMemorySize, GSMEM);
    cudaFuncSetAttribute(mma_gemm<3>, cudaFuncAttributeMaxDynamicSharedMemorySize, GSMEM);
    cudaFuncSetAttribute(logits_kernel, cudaFuncAttributeMaxDynamicSharedMemorySize, LT_SMEM);

    float *logits, *y;
    __half *xn, *vT, *pos, *rk, *probs, *o, *yn, *h1;
    __half *WqkT, *WvT, *WrT, *WoT, *W1T, *W2T;
    cudaGetSymbolAddress((void**)&logits, g_logits);
    cudaGetSymbolAddress((void**)&y, g_y);
    cudaGetSymbolAddress((void**)&xn, h_xn);
    cudaGetSymbolAddress((void**)&vT, h_vT);
    cudaGetSymbolAddress((void**)&pos, h_pos);
    cudaGetSymbolAddress((void**)&rk, h_rk);
    cudaGetSymbolAddress((void**)&probs, h_probs);
    cudaGetSymbolAddress((void**)&o, h_o);
    cudaGetSymbolAddress((void**)&yn, h_yn);
    cudaGetSymbolAddress((void**)&h1, h_h1);
    cudaGetSymbolAddress((void**)&WqkT, h_WqkT);
    cudaGetSymbolAddress((void**)&WvT, h_WvT);
    cudaGetSymbolAddress((void**)&WrT, h_WrT);
    cudaGetSymbolAddress((void**)&WoT, h_WoT);
    cudaGetSymbolAddress((void**)&W1T, h_W1T);
    cudaGetSymbolAddress((void**)&W2T, h_W2T);

    transpose_all<<<15456, dim3(32, 8)>>>(Wq, Wk, Wv, Wr, Wo, W1, W2);
    ln_kernel<<<Tq, 256>>>(x, ln1_g, ln1_b, xn);
    // fused QK: writes qw, qr, k
    mma_gemm<3><<<dim3(8, 12), 256, GSMEM>>>(
        xn, CC, 0, WqkT, CC, 0, nullptr, 0, 0, Tq, HK * 2, CC, rwb, rrb, 0);
    // vT = WvT @ xn^T
    mma_gemm<1><<<dim3(12, 12), 256, GSMEM>>>(
        WvT, CC, 0, xn, CC, 0, vT, Tq, 0, HV, Tq, CC, nullptr, nullptr, 0);
    posfeat_kernel<<<(T2 + 7) / 8, 256>>>(pos);
    mma_gemm<1><<<dim3(4, 24), 256, GSMEM>>>(
        pos, FF, 0, WrT, FF, 0, rk, HK, 0, T2, HK, FF, nullptr, nullptr, 0);
    // fused band logits
    logits_kernel<<<dim3(12, 12, NH), 256, LT_SMEM>>>(logits);
    softmax_kernel<<<dim3(Tq, NH), 256>>>(logits, probs);
    // o = probs @ v
    mma_gemm<1><<<dim3(2, 12, NH), 256, GSMEM>>>(
        probs, Tq, (long long)Tq * Tq, vT, Tq, (long long)VH * Tq,
        o, HV, VH, Tq, VH, Tq, nullptr, nullptr, 0);
    // y = x + o @ Wo + bo
    mma_gemm<0><<<dim3(12, 12), 256, GSMEM>>>(
        o, HV, 0, WoT, HV, 0, y, CC, 0, Tq, CC, HV, bo, x, 0);
    ln_kernel<<<Tq, 256>>>(y, ln2_g, ln2_b, yn);
    mma_gemm<1><<<dim3(24, 12), 256, GSMEM>>>(
        yn, CC, 0, W1T, CC, 0, h1, D1, 0, Tq, D1, CC, b1, nullptr, 1);
    mma_gemm<0><<<dim3(12, 12), 256, GSMEM>>>(
        h1, D1, 0, W2T, D1, 0, out, CC, 0, Tq, CC, D1, b2, y, 0);
}